// round 1
// baseline (speedup 1.0000x reference)
#include <cuda_runtime.h>
#include <cuda_bf16.h>
#include <cstdint>

#define NND 100000
#define NE  1600000
#define KF  256
#define OD  128

// ---------------- device scratch (no allocations allowed) ----------------
__device__ int   g_is64;
__device__ int   g_row[NE];
__device__ int   g_col[NE];
__device__ int   g_deg[NND];
__device__ float g_dinv[NND];
__device__ float g_h[(size_t)NND * OD];   // 51.2 MB

// ---------------- dtype detection for edge_index (int64 vs int32) -------
// If the data is really int32 node-id pairs, reading as int64 combines two
// ids: value = lo + hi*2^32 >= 2^32 unless hi==0 (prob ~1e-5 per element).
// 16 consecutive in-range int64 reads => data is genuinely int64.
__global__ void detect_kernel(const void* ei) {
    if (threadIdx.x == 0 && blockIdx.x == 0) {
        const long long* p = (const long long*)ei;
        int ok64 = 1;
        #pragma unroll
        for (int i = 0; i < 16; i++) {
            long long v = p[i];
            if (v < 0 || v >= NND) ok64 = 0;
        }
        g_is64 = ok64;
    }
}

__global__ void convert_edges(const void* ei) {
    int e = blockIdx.x * blockDim.x + threadIdx.x;
    if (e >= NE) return;
    if (g_is64) {
        const long long* p = (const long long*)ei;
        g_row[e] = (int)p[e];
        g_col[e] = (int)p[e + NE];
    } else {
        const int* p = (const int*)ei;
        g_row[e] = p[e];
        g_col[e] = p[e + NE];
    }
}

// ---------------- degree / normalization ----------------
__global__ void deg_init_kernel() {
    int i = blockIdx.x * blockDim.x + threadIdx.x;
    if (i < NND) g_deg[i] = 1;           // self loop
}

__global__ void deg_count_kernel() {
    int e = blockIdx.x * blockDim.x + threadIdx.x;
    if (e < NE) atomicAdd(&g_deg[g_col[e]], 1);
}

__global__ void dinv_kernel() {
    int i = blockIdx.x * blockDim.x + threadIdx.x;
    if (i < NND) g_dinv[i] = rsqrtf((float)g_deg[i]);
}

// ---------------- GEMM: h = x @ W + b  (fp32, FFMA2 via f32x2) ----------
// 128x128 output tile, BK=16, 256 threads, each thread 8 rows x 8 cols
// (held as 8x4 packed f32x2 accumulators).
__global__ __launch_bounds__(256) void gemm_kernel(
    const float* __restrict__ x,
    const float* __restrict__ W,
    const float* __restrict__ bias)
{
    __shared__ float As[16][128];   // [k][m]
    __shared__ float Bs[16][128];   // [k][n]

    const int tid = threadIdx.x;
    const int tx  = tid & 15;       // col group (8 cols each)
    const int ty  = tid >> 4;       // row group (8 rows each)
    const int rowBase = blockIdx.x * 128;

    unsigned long long acc[8][4];
    #pragma unroll
    for (int i = 0; i < 8; i++)
        #pragma unroll
        for (int j = 0; j < 4; j++) acc[i][j] = 0ull;

    for (int k0 = 0; k0 < KF; k0 += 16) {
        // ---- load x tile (128 rows x 16 k) into As transposed ----
        #pragma unroll
        for (int pass = 0; pass < 2; pass++) {
            int r  = (tid >> 2) + pass * 64;
            int c4 = (tid & 3) * 4;
            int gr = rowBase + r;
            float4 v = make_float4(0.f, 0.f, 0.f, 0.f);
            if (gr < NND)
                v = *(const float4*)(x + (size_t)gr * KF + k0 + c4);
            As[c4 + 0][r] = v.x;
            As[c4 + 1][r] = v.y;
            As[c4 + 2][r] = v.z;
            As[c4 + 3][r] = v.w;
        }
        // ---- load W tile (16 k x 128 n) into Bs ----
        #pragma unroll
        for (int pass = 0; pass < 2; pass++) {
            int idx = tid + pass * 256;
            int kr  = idx >> 5;
            int c4  = (idx & 31) * 4;
            float4 v = *(const float4*)(W + (size_t)(k0 + kr) * OD + c4);
            *(float4*)(&Bs[kr][c4]) = v;
        }
        __syncthreads();

        #pragma unroll
        for (int k = 0; k < 16; k++) {
            float a[8];
            unsigned long long ad[8], bp[4];
            #pragma unroll
            for (int i = 0; i < 8; i++) a[i] = As[k][ty * 8 + i];
            const unsigned long long* brow =
                (const unsigned long long*)&Bs[k][tx * 8];
            #pragma unroll
            for (int j = 0; j < 4; j++) bp[j] = brow[j];
            #pragma unroll
            for (int i = 0; i < 8; i++)
                asm("mov.b64 %0, {%1, %1};" : "=l"(ad[i]) : "f"(a[i]));
            #pragma unroll
            for (int i = 0; i < 8; i++)
                #pragma unroll
                for (int j = 0; j < 4; j++)
                    asm("fma.rn.f32x2 %0, %1, %2, %0;"
                        : "+l"(acc[i][j]) : "l"(ad[i]), "l"(bp[j]));
        }
        __syncthreads();
    }

    // ---- epilogue: add bias, store h ----
    #pragma unroll
    for (int i = 0; i < 8; i++) {
        int gr = rowBase + ty * 8 + i;
        if (gr < NND) {
            float* hp = g_h + (size_t)gr * OD + tx * 8;
            #pragma unroll
            for (int j = 0; j < 4; j++) {
                unsigned long long v = acc[i][j];
                float lo = __uint_as_float((unsigned)(v & 0xffffffffu));
                float hi = __uint_as_float((unsigned)(v >> 32));
                int c = tx * 8 + j * 2;
                hp[j * 2 + 0] = lo + bias[c];
                hp[j * 2 + 1] = hi + bias[c + 1];
            }
        }
    }
}

// ---------------- self-loop init: out[i,:] = h[i,:] * dinv[i]^2 ----------
__global__ void init_out_kernel(float* __restrict__ out) {
    int idx = blockIdx.x * blockDim.x + threadIdx.x;   // over NND*32 float4s
    if (idx >= NND * 32) return;
    int node = idx >> 5;
    float s = g_dinv[node];
    s = s * s;
    float4 v = *(const float4*)(g_h + (size_t)idx * 4);
    float4 o = make_float4(v.x * s, v.y * s, v.z * s, v.w * s);
    *(float4*)(out + (size_t)idx * 4) = o;
}

// ---------------- edge scatter: one warp per edge, vector RED ------------
__global__ __launch_bounds__(256) void scatter_kernel(float* __restrict__ out) {
    long long gid = (long long)blockIdx.x * blockDim.x + threadIdx.x;
    int e = (int)(gid >> 5);
    if (e >= NE) return;
    int lane = threadIdx.x & 31;
    int r = g_row[e];
    int c = g_col[e];
    float norm = g_dinv[r] * g_dinv[c];
    float4 v = *(const float4*)(g_h + (size_t)r * OD + lane * 4);
    float* p = out + (size_t)c * OD + lane * 4;
    asm volatile("red.global.add.v4.f32 [%0], {%1, %2, %3, %4};"
                 :: "l"(p), "f"(v.x * norm), "f"(v.y * norm),
                    "f"(v.z * norm), "f"(v.w * norm)
                 : "memory");
}

// ---------------- ReLU ----------------
__global__ void relu_kernel(float* __restrict__ out) {
    int idx = blockIdx.x * blockDim.x + threadIdx.x;   // over NND*32 float4s
    if (idx >= NND * 32) return;
    float4 v = *(float4*)(out + (size_t)idx * 4);
    v.x = fmaxf(v.x, 0.f);
    v.y = fmaxf(v.y, 0.f);
    v.z = fmaxf(v.z, 0.f);
    v.w = fmaxf(v.w, 0.f);
    *(float4*)(out + (size_t)idx * 4) = v;
}

// ---------------- launch ----------------
extern "C" void kernel_launch(void* const* d_in, const int* in_sizes, int n_in,
                              void* d_out, int out_size) {
    const float* x  = (const float*)d_in[0];
    const void*  ei = d_in[1];
    const float* W  = (const float*)d_in[2];
    const float* b  = (const float*)d_in[3];
    float* out = (float*)d_out;

    detect_kernel<<<1, 1>>>(ei);
    convert_edges<<<(NE + 255) / 256, 256>>>(ei);
    deg_init_kernel<<<(NND + 255) / 256, 256>>>();
    deg_count_kernel<<<(NE + 255) / 256, 256>>>();
    dinv_kernel<<<(NND + 255) / 256, 256>>>();
    gemm_kernel<<<(NND + 127) / 128, 256>>>(x, W, b);
    init_out_kernel<<<(NND * 32 + 255) / 256, 256>>>(out);
    scatter_kernel<<<(NE * 32) / 256, 256>>>(out);
    relu_kernel<<<(NND * 32 + 255) / 256, 256>>>(out);
}

// round 3
// speedup vs baseline: 1.2718x; 1.2718x over previous
#include <cuda_runtime.h>
#include <cuda_bf16.h>
#include <cstdint>

#define NND 100000
#define NE  1600000
#define KF  256
#define OD  128

// ---------------- device scratch (no allocations allowed) ----------------
__device__ int   g_is64;
__device__ int   g_row[NE];
__device__ int   g_col[NE];
__device__ int   g_deg[NND];
__device__ float g_dinv[NND];
__device__ float g_h[(size_t)NND * OD];             // 51.2 MB
__device__ __nv_bfloat16 g_wt_hi[OD * KF];          // W^T hi split [n][k]
__device__ __nv_bfloat16 g_wt_lo[OD * KF];          // W^T lo split [n][k]

__device__ __forceinline__ uint32_t smem_u32(const void* p) {
    uint32_t a;
    asm("{ .reg .u64 t; cvta.to.shared.u64 t, %1; cvt.u32.u64 %0, t; }"
        : "=r"(a) : "l"(p));
    return a;
}

// ---------------- dtype detection for edge_index (int64 vs int32) -------
__global__ void detect_kernel(const void* ei) {
    if (threadIdx.x == 0 && blockIdx.x == 0) {
        const long long* p = (const long long*)ei;
        int ok64 = 1;
        #pragma unroll
        for (int i = 0; i < 16; i++) {
            long long v = p[i];
            if (v < 0 || v >= NND) ok64 = 0;
        }
        g_is64 = ok64;
    }
}

__global__ void convert_edges(const void* ei) {
    int e = blockIdx.x * blockDim.x + threadIdx.x;
    if (e >= NE) return;
    if (g_is64) {
        const long long* p = (const long long*)ei;
        g_row[e] = (int)p[e];
        g_col[e] = (int)p[e + NE];
    } else {
        const int* p = (const int*)ei;
        g_row[e] = p[e];
        g_col[e] = p[e + NE];
    }
}

// ---------------- degree / normalization ----------------
__global__ void deg_init_kernel() {
    int i = blockIdx.x * blockDim.x + threadIdx.x;
    if (i < NND) g_deg[i] = 1;
}
__global__ void deg_count_kernel() {
    int e = blockIdx.x * blockDim.x + threadIdx.x;
    if (e < NE) atomicAdd(&g_deg[g_col[e]], 1);
}
__global__ void dinv_kernel() {
    int i = blockIdx.x * blockDim.x + threadIdx.x;
    if (i < NND) g_dinv[i] = rsqrtf((float)g_deg[i]);
}

// ---------------- W transpose + bf16 hi/lo split -------------------------
__global__ void wsplit_kernel(const float* __restrict__ W) {
    int idx = blockIdx.x * blockDim.x + threadIdx.x;
    if (idx >= KF * OD) return;
    int k = idx >> 7;
    int n = idx & 127;
    float v = W[idx];
    __nv_bfloat16 h = __float2bfloat16_rn(v);
    __nv_bfloat16 l = __float2bfloat16_rn(v - __bfloat162float(h));
    g_wt_hi[n * KF + k] = h;
    g_wt_lo[n * KF + k] = l;
}

// ================= GEMM via mma.sync bf16 (split hi/lo) =================
// CTA tile 128x128, K chunks of 64. 8 warps in 4(M)x2(N) grid,
// warp tile 32(M)x64(N). D = xh*Wh + xh*Wl + xl*Wh, fp32 accum.
static constexpr int SA = 72;                   // smem stride (bf16 elems), 144B
static constexpr int TILE_ELEMS = 128 * SA;     // per buffer
static constexpr int SMEM_DYN = 4 * TILE_ELEMS * 2;   // 73728 B

__device__ __forceinline__ unsigned pack_bf16x2(__nv_bfloat16 a, __nv_bfloat16 b) {
    return (unsigned)__bfloat16_as_ushort(a) | ((unsigned)__bfloat16_as_ushort(b) << 16);
}

__device__ __forceinline__ void ldmx4(uint32_t addr, uint32_t* r) {
    asm volatile("ldmatrix.sync.aligned.m8n8.x4.shared.b16 {%0,%1,%2,%3}, [%4];"
                 : "=r"(r[0]), "=r"(r[1]), "=r"(r[2]), "=r"(r[3]) : "r"(addr));
}

__device__ __forceinline__ void mma16816(float* d, const uint32_t* a,
                                         const uint32_t* b) {
    asm volatile(
        "mma.sync.aligned.m16n8k16.row.col.f32.bf16.bf16.f32 "
        "{%0,%1,%2,%3}, {%4,%5,%6,%7}, {%8,%9}, {%0,%1,%2,%3};"
        : "+f"(d[0]), "+f"(d[1]), "+f"(d[2]), "+f"(d[3])
        : "r"(a[0]), "r"(a[1]), "r"(a[2]), "r"(a[3]), "r"(b[0]), "r"(b[1]));
}

__global__ __launch_bounds__(256) void gemm_mma_kernel(
    const float* __restrict__ x, const float* __restrict__ bias)
{
    extern __shared__ __nv_bfloat16 sm[];
    __nv_bfloat16* sAh = sm;
    __nv_bfloat16* sAl = sAh + TILE_ELEMS;
    __nv_bfloat16* sBh = sAl + TILE_ELEMS;
    __nv_bfloat16* sBl = sBh + TILE_ELEMS;

    const int tid = threadIdx.x;
    const int wid = tid >> 5;
    const int lane = tid & 31;
    const int wm = wid & 3;          // 0..3 -> rows wm*32
    const int wn = wid >> 2;         // 0..1 -> cols wn*64
    const int rowBase = blockIdx.x * 128;

    float acc[2][8][4];
    #pragma unroll
    for (int i = 0; i < 2; i++)
        #pragma unroll
        for (int j = 0; j < 8; j++)
            #pragma unroll
            for (int q = 0; q < 4; q++) acc[i][j][q] = 0.f;

    // precompute ldmatrix lane offsets
    const int a_row_off = (lane & 7) + ((lane >> 3) & 1) * 8;  // within m16
    const int a_col_off = ((lane >> 4) & 1) * 8;               // within k16
    const int b_n_off   = (lane & 7) + ((lane >> 4) & 1) * 8;  // within n16
    const int b_k_off   = ((lane >> 3) & 1) * 8;               // within k16

    const uint32_t sAh_base = smem_u32(sAh);
    const uint32_t sAl_base = smem_u32(sAl);
    const uint32_t sBh_base = smem_u32(sBh);
    const uint32_t sBl_base = smem_u32(sBl);

    for (int c = 0; c < 4; c++) {
        const int k0 = c * 64;
        // ---- load A (x rows), split hi/lo ----
        #pragma unroll
        for (int i = 0; i < 8; i++) {
            int g = tid + i * 256;        // 0..2047
            int r = g >> 4;
            int f4 = g & 15;
            int grow = rowBase + r;
            float4 v = make_float4(0.f, 0.f, 0.f, 0.f);
            if (grow < NND)
                v = *(const float4*)(x + (size_t)grow * KF + k0 + f4 * 4);
            __nv_bfloat16 hx = __float2bfloat16_rn(v.x);
            __nv_bfloat16 hy = __float2bfloat16_rn(v.y);
            __nv_bfloat16 hz = __float2bfloat16_rn(v.z);
            __nv_bfloat16 hw = __float2bfloat16_rn(v.w);
            __nv_bfloat16 lx = __float2bfloat16_rn(v.x - __bfloat162float(hx));
            __nv_bfloat16 ly = __float2bfloat16_rn(v.y - __bfloat162float(hy));
            __nv_bfloat16 lz = __float2bfloat16_rn(v.z - __bfloat162float(hz));
            __nv_bfloat16 lw = __float2bfloat16_rn(v.w - __bfloat162float(hw));
            int off = r * SA + f4 * 4;
            *(uint2*)(sAh + off) = make_uint2(pack_bf16x2(hx, hy), pack_bf16x2(hz, hw));
            *(uint2*)(sAl + off) = make_uint2(pack_bf16x2(lx, ly), pack_bf16x2(lz, lw));
        }
        // ---- load B (pre-split W^T [n][k]) ----
        #pragma unroll
        for (int i = 0; i < 8; i++) {
            int g = tid + i * 256;
            int n = g >> 4;
            int f4 = g & 15;
            size_t src = (size_t)n * KF + k0 + f4 * 4;
            int off = n * SA + f4 * 4;
            *(uint2*)(sBh + off) = *(const uint2*)(g_wt_hi + src);
            *(uint2*)(sBl + off) = *(const uint2*)(g_wt_lo + src);
        }
        __syncthreads();

        #pragma unroll
        for (int ks = 0; ks < 4; ks++) {
            const int k = ks * 16;
            uint32_t af[2][2][4];    // [hi/lo][mtile][4]
            #pragma unroll
            for (int mt = 0; mt < 2; mt++) {
                int row = wm * 32 + mt * 16 + a_row_off;
                uint32_t byoff = (uint32_t)(row * SA + k + a_col_off) * 2;
                ldmx4(sAh_base + byoff, af[0][mt]);
                ldmx4(sAl_base + byoff, af[1][mt]);
            }
            uint32_t bf[2][4][4];    // [hi/lo][n16-group][4]
            #pragma unroll
            for (int j = 0; j < 4; j++) {
                int n = wn * 64 + j * 16 + b_n_off;
                uint32_t byoff = (uint32_t)(n * SA + k + b_k_off) * 2;
                ldmx4(sBh_base + byoff, bf[0][j]);
                ldmx4(sBl_base + byoff, bf[1][j]);
            }
            #pragma unroll
            for (int mt = 0; mt < 2; mt++)
                #pragma unroll
                for (int j = 0; j < 4; j++)
                    #pragma unroll
                    for (int h = 0; h < 2; h++) {
                        int nt = j * 2 + h;
                        mma16816(acc[mt][nt], af[0][mt], &bf[0][j][h * 2]); // xh*Wh
                        mma16816(acc[mt][nt], af[0][mt], &bf[1][j][h * 2]); // xh*Wl
                        mma16816(acc[mt][nt], af[1][mt], &bf[0][j][h * 2]); // xl*Wh
                    }
        }
        __syncthreads();
    }

    // ---- epilogue: acc -> g_h with bias ----
    const int g4 = lane >> 2;       // 0..7
    const int ti = lane & 3;        // 0..3
    #pragma unroll
    for (int mt = 0; mt < 2; mt++) {
        #pragma unroll
        for (int nt = 0; nt < 8; nt++) {
            int col = wn * 64 + nt * 8 + ti * 2;
            float b0 = bias[col], b1 = bias[col + 1];
            int r0 = rowBase + wm * 32 + mt * 16 + g4;
            if (r0 < NND) {
                float2 o = make_float2(acc[mt][nt][0] + b0, acc[mt][nt][1] + b1);
                *(float2*)(g_h + (size_t)r0 * OD + col) = o;
            }
            int r1 = r0 + 8;
            if (r1 < NND) {
                float2 o = make_float2(acc[mt][nt][2] + b0, acc[mt][nt][3] + b1);
                *(float2*)(g_h + (size_t)r1 * OD + col) = o;
            }
        }
    }
}

// ---------------- self-loop init: out[i,:] = h[i,:] * dinv[i]^2 ----------
__global__ void init_out_kernel(float* __restrict__ out) {
    int idx = blockIdx.x * blockDim.x + threadIdx.x;
    if (idx >= NND * 32) return;
    int node = idx >> 5;
    float s = g_dinv[node];
    s = s * s;
    float4 v = *(const float4*)(g_h + (size_t)idx * 4);
    float4 o = make_float4(v.x * s, v.y * s, v.z * s, v.w * s);
    *(float4*)(out + (size_t)idx * 4) = o;
}

// ---------------- edge scatter: one warp per edge, vector RED ------------
__global__ __launch_bounds__(256) void scatter_kernel(float* __restrict__ out) {
    long long gid = (long long)blockIdx.x * blockDim.x + threadIdx.x;
    int e = (int)(gid >> 5);
    if (e >= NE) return;
    int lane = threadIdx.x & 31;
    int r = g_row[e];
    int c = g_col[e];
    float norm = g_dinv[r] * g_dinv[c];
    float4 v = *(const float4*)(g_h + (size_t)r * OD + lane * 4);
    float* p = out + (size_t)c * OD + lane * 4;
    asm volatile("red.global.add.v4.f32 [%0], {%1, %2, %3, %4};"
                 :: "l"(p), "f"(v.x * norm), "f"(v.y * norm),
                    "f"(v.z * norm), "f"(v.w * norm)
                 : "memory");
}

// ---------------- ReLU ----------------
__global__ void relu_kernel(float* __restrict__ out) {
    int idx = blockIdx.x * blockDim.x + threadIdx.x;
    if (idx >= NND * 32) return;
    float4 v = *(float4*)(out + (size_t)idx * 4);
    v.x = fmaxf(v.x, 0.f);
    v.y = fmaxf(v.y, 0.f);
    v.z = fmaxf(v.z, 0.f);
    v.w = fmaxf(v.w, 0.f);
    *(float4*)(out + (size_t)idx * 4) = v;
}

// ---------------- launch ----------------
extern "C" void kernel_launch(void* const* d_in, const int* in_sizes, int n_in,
                              void* d_out, int out_size) {
    const float* x  = (const float*)d_in[0];
    const void*  ei = d_in[1];
    const float* W  = (const float*)d_in[2];
    const float* b  = (const float*)d_in[3];
    float* out = (float*)d_out;

    cudaFuncSetAttribute(gemm_mma_kernel,
                         cudaFuncAttributeMaxDynamicSharedMemorySize, SMEM_DYN);

    detect_kernel<<<1, 1>>>(ei);
    convert_edges<<<(NE + 255) / 256, 256>>>(ei);
    deg_init_kernel<<<(NND + 255) / 256, 256>>>();
    deg_count_kernel<<<(NE + 255) / 256, 256>>>();
    dinv_kernel<<<(NND + 255) / 256, 256>>>();
    wsplit_kernel<<<(KF * OD + 255) / 256, 256>>>(W);
    gemm_mma_kernel<<<(NND + 127) / 128, 256, SMEM_DYN>>>(x, b);
    init_out_kernel<<<(NND * 32 + 255) / 256, 256>>>(out);
    scatter_kernel<<<(NE * 32) / 256, 256>>>(out);
    relu_kernel<<<(NND * 32 + 255) / 256, 256>>>(out);
}

// round 4
// speedup vs baseline: 1.4718x; 1.1573x over previous
#include <cuda_runtime.h>
#include <cuda_bf16.h>
#include <cstdint>

#define NND 100000
#define NE  1600000
#define KF  256
#define OD  128

// ---------------- device scratch (no allocations allowed) ----------------
__device__ int   g_is64;
__device__ int   g_row[NE];
__device__ int   g_col[NE];
__device__ int   g_srt[NE];          // CSR: source idx sorted by destination
__device__ int   g_deg[NND];         // in-degree WITHOUT self loop
__device__ int   g_start[NND];       // CSR row starts (exclusive scan of deg)
__device__ int   g_pos[NND];         // fill cursors
__device__ float g_dinv[NND];
__device__ float g_h[(size_t)NND * OD];             // hs = dinv * (xW+b), 51.2 MB
__device__ __nv_bfloat16 g_wt_hi[OD * KF];
__device__ __nv_bfloat16 g_wt_lo[OD * KF];

__device__ __forceinline__ uint32_t smem_u32(const void* p) {
    uint32_t a;
    asm("{ .reg .u64 t; cvta.to.shared.u64 t, %1; cvt.u32.u64 %0, t; }"
        : "=r"(a) : "l"(p));
    return a;
}

// ---------------- dtype detection for edge_index (int64 vs int32) -------
__global__ void detect_kernel(const void* ei) {
    if (threadIdx.x == 0 && blockIdx.x == 0) {
        const long long* p = (const long long*)ei;
        int ok64 = 1;
        #pragma unroll
        for (int i = 0; i < 16; i++) {
            long long v = p[i];
            if (v < 0 || v >= NND) ok64 = 0;
        }
        g_is64 = ok64;
    }
}

__global__ void convert_edges(const void* ei) {
    int e = blockIdx.x * blockDim.x + threadIdx.x;
    if (e >= NE) return;
    if (g_is64) {
        const long long* p = (const long long*)ei;
        g_row[e] = (int)p[e];
        g_col[e] = (int)p[e + NE];
    } else {
        const int* p = (const int*)ei;
        g_row[e] = p[e];
        g_col[e] = p[e + NE];
    }
}

// ---------------- degree / normalization ----------------
__global__ void zero_kernel() {
    int i = blockIdx.x * blockDim.x + threadIdx.x;
    if (i < NND) { g_deg[i] = 0; g_pos[i] = 0; }
}
__global__ void deg_count_kernel() {
    int e = blockIdx.x * blockDim.x + threadIdx.x;
    if (e < NE) atomicAdd(&g_deg[g_col[e]], 1);
}
__global__ void dinv_kernel() {
    int i = blockIdx.x * blockDim.x + threadIdx.x;
    if (i < NND) g_dinv[i] = rsqrtf((float)(g_deg[i] + 1));  // +1 self loop
}

// ---------------- exclusive scan of g_deg -> g_start (single block) ------
__global__ __launch_bounds__(1024) void scan_kernel() {
    __shared__ int part[1024];
    const int t = threadIdx.x;
    const int C = (NND + 1023) / 1024;          // 98
    const int base = t * C;
    int s = 0;
    for (int j = 0; j < C; j++) {
        int i = base + j;
        if (i < NND) s += g_deg[i];
    }
    part[t] = s;
    __syncthreads();
    // Hillis-Steele inclusive scan
    for (int off = 1; off < 1024; off <<= 1) {
        int v = (t >= off) ? part[t - off] : 0;
        __syncthreads();
        part[t] += v;
        __syncthreads();
    }
    int run = (t == 0) ? 0 : part[t - 1];
    for (int j = 0; j < C; j++) {
        int i = base + j;
        if (i < NND) { g_start[i] = run; run += g_deg[i]; }
    }
}

// ---------------- CSR fill (counting sort by destination) ----------------
__global__ void fill_kernel() {
    int e = blockIdx.x * blockDim.x + threadIdx.x;
    if (e >= NE) return;
    int c = g_col[e];
    int pos = g_start[c] + atomicAdd(&g_pos[c], 1);
    g_srt[pos] = g_row[e];
}

// ---------------- W transpose + bf16 hi/lo split -------------------------
__global__ void wsplit_kernel(const float* __restrict__ W) {
    int idx = blockIdx.x * blockDim.x + threadIdx.x;
    if (idx >= KF * OD) return;
    int k = idx >> 7;
    int n = idx & 127;
    float v = W[idx];
    __nv_bfloat16 h = __float2bfloat16_rn(v);
    __nv_bfloat16 l = __float2bfloat16_rn(v - __bfloat162float(h));
    g_wt_hi[n * KF + k] = h;
    g_wt_lo[n * KF + k] = l;
}

// ================= GEMM via mma.sync bf16 (split hi/lo) =================
// CTA tile 128x128, K chunks of 64. 8 warps in 4(M)x2(N) grid,
// warp tile 32(M)x64(N). D = xh*Wh + xh*Wl + xl*Wh, fp32 accum.
// Epilogue fuses hs = dinv[row] * (D + bias).
static constexpr int SA = 72;
static constexpr int TILE_ELEMS = 128 * SA;
static constexpr int SMEM_DYN = 4 * TILE_ELEMS * 2;   // 73728 B

__device__ __forceinline__ unsigned pack_bf16x2(__nv_bfloat16 a, __nv_bfloat16 b) {
    return (unsigned)__bfloat16_as_ushort(a) | ((unsigned)__bfloat16_as_ushort(b) << 16);
}

__device__ __forceinline__ void ldmx4(uint32_t addr, uint32_t* r) {
    asm volatile("ldmatrix.sync.aligned.m8n8.x4.shared.b16 {%0,%1,%2,%3}, [%4];"
                 : "=r"(r[0]), "=r"(r[1]), "=r"(r[2]), "=r"(r[3]) : "r"(addr));
}

__device__ __forceinline__ void mma16816(float* d, const uint32_t* a,
                                         const uint32_t* b) {
    asm volatile(
        "mma.sync.aligned.m16n8k16.row.col.f32.bf16.bf16.f32 "
        "{%0,%1,%2,%3}, {%4,%5,%6,%7}, {%8,%9}, {%0,%1,%2,%3};"
        : "+f"(d[0]), "+f"(d[1]), "+f"(d[2]), "+f"(d[3])
        : "r"(a[0]), "r"(a[1]), "r"(a[2]), "r"(a[3]), "r"(b[0]), "r"(b[1]));
}

__global__ __launch_bounds__(256) void gemm_mma_kernel(
    const float* __restrict__ x, const float* __restrict__ bias)
{
    extern __shared__ __nv_bfloat16 sm[];
    __nv_bfloat16* sAh = sm;
    __nv_bfloat16* sAl = sAh + TILE_ELEMS;
    __nv_bfloat16* sBh = sAl + TILE_ELEMS;
    __nv_bfloat16* sBl = sBh + TILE_ELEMS;

    const int tid = threadIdx.x;
    const int wid = tid >> 5;
    const int lane = tid & 31;
    const int wm = wid & 3;
    const int wn = wid >> 2;
    const int rowBase = blockIdx.x * 128;

    float acc[2][8][4];
    #pragma unroll
    for (int i = 0; i < 2; i++)
        #pragma unroll
        for (int j = 0; j < 8; j++)
            #pragma unroll
            for (int q = 0; q < 4; q++) acc[i][j][q] = 0.f;

    const int a_row_off = (lane & 7) + ((lane >> 3) & 1) * 8;
    const int a_col_off = ((lane >> 4) & 1) * 8;
    const int b_n_off   = (lane & 7) + ((lane >> 4) & 1) * 8;
    const int b_k_off   = ((lane >> 3) & 1) * 8;

    const uint32_t sAh_base = smem_u32(sAh);
    const uint32_t sAl_base = smem_u32(sAl);
    const uint32_t sBh_base = smem_u32(sBh);
    const uint32_t sBl_base = smem_u32(sBl);

    for (int c = 0; c < 4; c++) {
        const int k0 = c * 64;
        #pragma unroll
        for (int i = 0; i < 8; i++) {
            int g = tid + i * 256;
            int r = g >> 4;
            int f4 = g & 15;
            int grow = rowBase + r;
            float4 v = make_float4(0.f, 0.f, 0.f, 0.f);
            if (grow < NND)
                v = *(const float4*)(x + (size_t)grow * KF + k0 + f4 * 4);
            __nv_bfloat16 hx = __float2bfloat16_rn(v.x);
            __nv_bfloat16 hy = __float2bfloat16_rn(v.y);
            __nv_bfloat16 hz = __float2bfloat16_rn(v.z);
            __nv_bfloat16 hw = __float2bfloat16_rn(v.w);
            __nv_bfloat16 lx = __float2bfloat16_rn(v.x - __bfloat162float(hx));
            __nv_bfloat16 ly = __float2bfloat16_rn(v.y - __bfloat162float(hy));
            __nv_bfloat16 lz = __float2bfloat16_rn(v.z - __bfloat162float(hz));
            __nv_bfloat16 lw = __float2bfloat16_rn(v.w - __bfloat162float(hw));
            int off = r * SA + f4 * 4;
            *(uint2*)(sAh + off) = make_uint2(pack_bf16x2(hx, hy), pack_bf16x2(hz, hw));
            *(uint2*)(sAl + off) = make_uint2(pack_bf16x2(lx, ly), pack_bf16x2(lz, lw));
        }
        #pragma unroll
        for (int i = 0; i < 8; i++) {
            int g = tid + i * 256;
            int n = g >> 4;
            int f4 = g & 15;
            size_t src = (size_t)n * KF + k0 + f4 * 4;
            int off = n * SA + f4 * 4;
            *(uint2*)(sBh + off) = *(const uint2*)(g_wt_hi + src);
            *(uint2*)(sBl + off) = *(const uint2*)(g_wt_lo + src);
        }
        __syncthreads();

        #pragma unroll
        for (int ks = 0; ks < 4; ks++) {
            const int k = ks * 16;
            uint32_t af[2][2][4];
            #pragma unroll
            for (int mt = 0; mt < 2; mt++) {
                int row = wm * 32 + mt * 16 + a_row_off;
                uint32_t byoff = (uint32_t)(row * SA + k + a_col_off) * 2;
                ldmx4(sAh_base + byoff, af[0][mt]);
                ldmx4(sAl_base + byoff, af[1][mt]);
            }
            uint32_t bf[2][4][4];
            #pragma unroll
            for (int j = 0; j < 4; j++) {
                int n = wn * 64 + j * 16 + b_n_off;
                uint32_t byoff = (uint32_t)(n * SA + k + b_k_off) * 2;
                ldmx4(sBh_base + byoff, bf[0][j]);
                ldmx4(sBl_base + byoff, bf[1][j]);
            }
            #pragma unroll
            for (int mt = 0; mt < 2; mt++)
                #pragma unroll
                for (int j = 0; j < 4; j++)
                    #pragma unroll
                    for (int h = 0; h < 2; h++) {
                        int nt = j * 2 + h;
                        mma16816(acc[mt][nt], af[0][mt], &bf[0][j][h * 2]);
                        mma16816(acc[mt][nt], af[0][mt], &bf[1][j][h * 2]);
                        mma16816(acc[mt][nt], af[1][mt], &bf[0][j][h * 2]);
                    }
        }
        __syncthreads();
    }

    // ---- epilogue: hs = dinv[row] * (acc + bias) ----
    const int g4 = lane >> 2;
    const int ti = lane & 3;
    #pragma unroll
    for (int mt = 0; mt < 2; mt++) {
        int r0 = rowBase + wm * 32 + mt * 16 + g4;
        int r1 = r0 + 8;
        float d0 = (r0 < NND) ? g_dinv[r0] : 0.f;
        float d1 = (r1 < NND) ? g_dinv[r1] : 0.f;
        #pragma unroll
        for (int nt = 0; nt < 8; nt++) {
            int col = wn * 64 + nt * 8 + ti * 2;
            float b0 = bias[col], b1 = bias[col + 1];
            if (r0 < NND) {
                float2 o = make_float2((acc[mt][nt][0] + b0) * d0,
                                       (acc[mt][nt][1] + b1) * d0);
                *(float2*)(g_h + (size_t)r0 * OD + col) = o;
            }
            if (r1 < NND) {
                float2 o = make_float2((acc[mt][nt][2] + b0) * d1,
                                       (acc[mt][nt][3] + b1) * d1);
                *(float2*)(g_h + (size_t)r1 * OD + col) = o;
            }
        }
    }
}

// ---------------- CSR aggregation: warp per node, fused ReLU -------------
__global__ __launch_bounds__(256) void agg_kernel(float* __restrict__ out) {
    int gid = blockIdx.x * 256 + threadIdx.x;
    int node = gid >> 5;
    if (node >= NND) return;
    int lane = threadIdx.x & 31;

    // self loop term (hs already includes dinv[node])
    float4 acc = *(const float4*)(g_h + (size_t)node * OD + lane * 4);

    int s = g_start[node];
    int e = s + g_deg[node];
    int i = s;
    for (; i + 2 <= e; i += 2) {
        int r0 = g_srt[i];
        int r1 = g_srt[i + 1];
        float4 v0 = *(const float4*)(g_h + (size_t)r0 * OD + lane * 4);
        float4 v1 = *(const float4*)(g_h + (size_t)r1 * OD + lane * 4);
        acc.x += v0.x + v1.x;
        acc.y += v0.y + v1.y;
        acc.z += v0.z + v1.z;
        acc.w += v0.w + v1.w;
    }
    if (i < e) {
        int r0 = g_srt[i];
        float4 v0 = *(const float4*)(g_h + (size_t)r0 * OD + lane * 4);
        acc.x += v0.x; acc.y += v0.y; acc.z += v0.z; acc.w += v0.w;
    }

    float d = g_dinv[node];
    float4 o;
    o.x = fmaxf(acc.x * d, 0.f);
    o.y = fmaxf(acc.y * d, 0.f);
    o.z = fmaxf(acc.z * d, 0.f);
    o.w = fmaxf(acc.w * d, 0.f);
    *(float4*)(out + (size_t)node * OD + lane * 4) = o;
}

// ---------------- launch ----------------
extern "C" void kernel_launch(void* const* d_in, const int* in_sizes, int n_in,
                              void* d_out, int out_size) {
    const float* x  = (const float*)d_in[0];
    const void*  ei = d_in[1];
    const float* W  = (const float*)d_in[2];
    const float* b  = (const float*)d_in[3];
    float* out = (float*)d_out;

    cudaFuncSetAttribute(gemm_mma_kernel,
                         cudaFuncAttributeMaxDynamicSharedMemorySize, SMEM_DYN);

    detect_kernel<<<1, 1>>>(ei);
    convert_edges<<<(NE + 255) / 256, 256>>>(ei);
    zero_kernel<<<(NND + 255) / 256, 256>>>();
    deg_count_kernel<<<(NE + 255) / 256, 256>>>();
    dinv_kernel<<<(NND + 255) / 256, 256>>>();
    scan_kernel<<<1, 1024>>>();
    fill_kernel<<<(NE + 255) / 256, 256>>>();
    wsplit_kernel<<<(KF * OD + 255) / 256, 256>>>(W);
    gemm_mma_kernel<<<(NND + 127) / 128, 256, SMEM_DYN>>>(x, b);
    agg_kernel<<<(NND * 32 + 255) / 256, 256>>>(out);
}

// round 5
// speedup vs baseline: 1.5576x; 1.0582x over previous
#include <cuda_runtime.h>
#include <cuda_bf16.h>
#include <cstdint>

#define NND 100000
#define NE  1600000
#define KF  256
#define OD  128

// ---------------- device scratch (no allocations allowed) ----------------
__device__ int   g_is64;
__device__ int   g_row[NE];
__device__ int   g_col[NE];
__device__ int   g_srt[NE];
__device__ int   g_deg[NND];
__device__ int   g_start[NND];
__device__ int   g_pos[NND];
__device__ float g_dinv[NND];
__device__ float g_h[(size_t)NND * OD];
__device__ __nv_bfloat16 g_wt_hi[OD * KF];
__device__ __nv_bfloat16 g_wt_lo[OD * KF];

__device__ __forceinline__ uint32_t smem_u32(const void* p) {
    uint32_t a;
    asm("{ .reg .u64 t; cvta.to.shared.u64 t, %1; cvt.u32.u64 %0, t; }"
        : "=r"(a) : "l"(p));
    return a;
}

#define CP_ASYNC16(dst, src) \
    asm volatile("cp.async.cg.shared.global [%0], [%1], 16;" \
                 :: "r"(dst), "l"(src) : "memory")
#define CP_COMMIT() asm volatile("cp.async.commit_group;" ::: "memory")
#define CP_WAIT0()  asm volatile("cp.async.wait_group 0;" ::: "memory")

// ---------------- zero + dtype detect (fused) ----------------------------
__global__ void zero_detect_kernel(const void* ei) {
    int i = blockIdx.x * blockDim.x + threadIdx.x;
    if (i < NND) { g_deg[i] = 0; g_pos[i] = 0; }
    if (i == 0) {
        const long long* p = (const long long*)ei;
        int ok64 = 1;
        #pragma unroll
        for (int j = 0; j < 16; j++) {
            long long v = p[j];
            if (v < 0 || v >= NND) ok64 = 0;
        }
        g_is64 = ok64;
    }
}

// ---------------- convert edges + degree count (fused) -------------------
__global__ void conv_deg_kernel(const void* ei) {
    int e = blockIdx.x * blockDim.x + threadIdx.x;
    if (e >= NE) return;
    int r, c;
    if (g_is64) {
        const long long* p = (const long long*)ei;
        r = (int)p[e];
        c = (int)p[e + NE];
    } else {
        const int* p = (const int*)ei;
        r = p[e];
        c = p[e + NE];
    }
    g_row[e] = r;
    g_col[e] = c;
    atomicAdd(&g_deg[c], 1);
}

__global__ void dinv_kernel() {
    int i = blockIdx.x * blockDim.x + threadIdx.x;
    if (i < NND) g_dinv[i] = rsqrtf((float)(g_deg[i] + 1));
}

// ---------------- exclusive scan of g_deg -> g_start (single block) ------
__global__ __launch_bounds__(1024) void scan_kernel() {
    __shared__ int part[1024];
    const int t = threadIdx.x;
    const int C = (NND + 1023) / 1024;
    const int base = t * C;
    int s = 0;
    for (int j = 0; j < C; j++) {
        int i = base + j;
        if (i < NND) s += g_deg[i];
    }
    part[t] = s;
    __syncthreads();
    for (int off = 1; off < 1024; off <<= 1) {
        int v = (t >= off) ? part[t - off] : 0;
        __syncthreads();
        part[t] += v;
        __syncthreads();
    }
    int run = (t == 0) ? 0 : part[t - 1];
    for (int j = 0; j < C; j++) {
        int i = base + j;
        if (i < NND) { g_start[i] = run; run += g_deg[i]; }
    }
}

// ---------------- CSR fill (counting sort by destination) ----------------
__global__ void fill_kernel() {
    int e = blockIdx.x * blockDim.x + threadIdx.x;
    if (e >= NE) return;
    int c = g_col[e];
    int pos = g_start[c] + atomicAdd(&g_pos[c], 1);
    g_srt[pos] = g_row[e];
}

// ---------------- W transpose + bf16 hi/lo split -------------------------
__global__ void wsplit_kernel(const float* __restrict__ W) {
    int idx = blockIdx.x * blockDim.x + threadIdx.x;
    if (idx >= KF * OD) return;
    int k = idx >> 7;
    int n = idx & 127;
    float v = W[idx];
    __nv_bfloat16 h = __float2bfloat16_rn(v);
    __nv_bfloat16 l = __float2bfloat16_rn(v - __bfloat162float(h));
    g_wt_hi[n * KF + k] = h;
    g_wt_lo[n * KF + k] = l;
}

// ================= GEMM via mma.sync bf16, double-buffered ==============
// CTA tile 128x128, K chunks of 64 (4 chunks). 8 warps 4(M)x2(N),
// warp tile 32x64. D = xh*Wh + xh*Wl + xl*Wh, fp32 accum.
// A: LDG->convert->STS (double buffered, loads issued pre-MMA).
// B: cp.async bf16 copy (double buffered).
// Epilogue fuses hs = dinv[row] * (D + bias).
static constexpr int SA = 72;
static constexpr int TILE_ELEMS = 128 * SA;
static constexpr int SMEM_DYN = 8 * TILE_ELEMS * 2;   // 147456 B

__device__ __forceinline__ unsigned pack_bf16x2(__nv_bfloat16 a, __nv_bfloat16 b) {
    return (unsigned)__bfloat16_as_ushort(a) | ((unsigned)__bfloat16_as_ushort(b) << 16);
}

__device__ __forceinline__ void ldmx4(uint32_t addr, uint32_t* r) {
    asm volatile("ldmatrix.sync.aligned.m8n8.x4.shared.b16 {%0,%1,%2,%3}, [%4];"
                 : "=r"(r[0]), "=r"(r[1]), "=r"(r[2]), "=r"(r[3]) : "r"(addr));
}

__device__ __forceinline__ void mma16816(float* d, const uint32_t* a,
                                         const uint32_t* b) {
    asm volatile(
        "mma.sync.aligned.m16n8k16.row.col.f32.bf16.bf16.f32 "
        "{%0,%1,%2,%3}, {%4,%5,%6,%7}, {%8,%9}, {%0,%1,%2,%3};"
        : "+f"(d[0]), "+f"(d[1]), "+f"(d[2]), "+f"(d[3])
        : "r"(a[0]), "r"(a[1]), "r"(a[2]), "r"(a[3]), "r"(b[0]), "r"(b[1]));
}

__global__ __launch_bounds__(256) void gemm_mma_kernel(
    const float* __restrict__ x, const float* __restrict__ bias)
{
    extern __shared__ __nv_bfloat16 sm[];
    // layout: Ah0 Al0 Ah1 Al1 Bh0 Bl0 Bh1 Bl1
    __nv_bfloat16* sAh[2] = { sm,                 sm + 2 * TILE_ELEMS };
    __nv_bfloat16* sAl[2] = { sm + TILE_ELEMS,    sm + 3 * TILE_ELEMS };
    __nv_bfloat16* sBh[2] = { sm + 4 * TILE_ELEMS, sm + 6 * TILE_ELEMS };
    __nv_bfloat16* sBl[2] = { sm + 5 * TILE_ELEMS, sm + 7 * TILE_ELEMS };

    const int tid = threadIdx.x;
    const int wid = tid >> 5;
    const int lane = tid & 31;
    const int wm = wid & 3;
    const int wn = wid >> 2;
    const int rowBase = blockIdx.x * 128;

    float acc[2][8][4];
    #pragma unroll
    for (int i = 0; i < 2; i++)
        #pragma unroll
        for (int j = 0; j < 8; j++)
            #pragma unroll
            for (int q = 0; q < 4; q++) acc[i][j][q] = 0.f;

    const int a_row_off = (lane & 7) + ((lane >> 3) & 1) * 8;
    const int a_col_off = ((lane >> 4) & 1) * 8;
    const int b_n_off   = (lane & 7) + ((lane >> 4) & 1) * 8;
    const int b_k_off   = ((lane >> 3) & 1) * 8;

    // per-thread A-load coords: 8 float4s
    const int ar  = tid >> 4;          // row 0..15 (+16*i later? no: g = tid + i*256)
    // We keep original mapping: g = tid + i*256; r = g>>4; f4 = g&15.

    // per-thread B cp.async coords: 4 ops per split: g = tid + i*256, n=g>>3, f8=g&7
    float4 areg[8];

    auto load_a = [&](int k0) {
        #pragma unroll
        for (int i = 0; i < 8; i++) {
            int g = tid + i * 256;
            int r = g >> 4;
            int f4 = g & 15;
            int grow = rowBase + r;
            areg[i] = make_float4(0.f, 0.f, 0.f, 0.f);
            if (grow < NND)
                areg[i] = *(const float4*)(x + (size_t)grow * KF + k0 + f4 * 4);
        }
    };
    auto store_a = [&](int buf) {
        #pragma unroll
        for (int i = 0; i < 8; i++) {
            int g = tid + i * 256;
            int r = g >> 4;
            int f4 = g & 15;
            float4 v = areg[i];
            __nv_bfloat16 hx = __float2bfloat16_rn(v.x);
            __nv_bfloat16 hy = __float2bfloat16_rn(v.y);
            __nv_bfloat16 hz = __float2bfloat16_rn(v.z);
            __nv_bfloat16 hw = __float2bfloat16_rn(v.w);
            __nv_bfloat16 lx = __float2bfloat16_rn(v.x - __bfloat162float(hx));
            __nv_bfloat16 ly = __float2bfloat16_rn(v.y - __bfloat162float(hy));
            __nv_bfloat16 lz = __float2bfloat16_rn(v.z - __bfloat162float(hz));
            __nv_bfloat16 lw = __float2bfloat16_rn(v.w - __bfloat162float(hw));
            int off = r * SA + f4 * 4;
            *(uint2*)(sAh[buf] + off) = make_uint2(pack_bf16x2(hx, hy), pack_bf16x2(hz, hw));
            *(uint2*)(sAl[buf] + off) = make_uint2(pack_bf16x2(lx, ly), pack_bf16x2(lz, lw));
        }
    };
    auto issue_b = [&](int k0, int buf) {
        uint32_t bh = smem_u32(sBh[buf]);
        uint32_t bl = smem_u32(sBl[buf]);
        #pragma unroll
        for (int i = 0; i < 4; i++) {
            int g = tid + i * 256;            // 0..1023
            int n = g >> 3;
            int f8 = g & 7;
            uint32_t doff = (uint32_t)(n * SA + f8 * 8) * 2;
            const __nv_bfloat16* srch = g_wt_hi + (size_t)n * KF + k0 + f8 * 8;
            const __nv_bfloat16* srcl = g_wt_lo + (size_t)n * KF + k0 + f8 * 8;
            CP_ASYNC16(bh + doff, srch);
            CP_ASYNC16(bl + doff, srcl);
        }
        CP_COMMIT();
    };

    // ---- prologue: chunk 0 ----
    load_a(0);
    issue_b(0, 0);
    store_a(0);
    CP_WAIT0();
    __syncthreads();

    for (int c = 0; c < 4; c++) {
        const int buf = c & 1;
        if (c < 3) {
            issue_b((c + 1) * 64, buf ^ 1);
            load_a((c + 1) * 64);          // LDGs in flight during MMA
        }

        const uint32_t ah_b = smem_u32(sAh[buf]);
        const uint32_t al_b = smem_u32(sAl[buf]);
        const uint32_t bh_b = smem_u32(sBh[buf]);
        const uint32_t bl_b = smem_u32(sBl[buf]);

        #pragma unroll
        for (int ks = 0; ks < 4; ks++) {
            const int k = ks * 16;
            uint32_t af[2][2][4];
            #pragma unroll
            for (int mt = 0; mt < 2; mt++) {
                int row = wm * 32 + mt * 16 + a_row_off;
                uint32_t byoff = (uint32_t)(row * SA + k + a_col_off) * 2;
                ldmx4(ah_b + byoff, af[0][mt]);
                ldmx4(al_b + byoff, af[1][mt]);
            }
            uint32_t bfg[2][4][4];
            #pragma unroll
            for (int j = 0; j < 4; j++) {
                int n = wn * 64 + j * 16 + b_n_off;
                uint32_t byoff = (uint32_t)(n * SA + k + b_k_off) * 2;
                ldmx4(bh_b + byoff, bfg[0][j]);
                ldmx4(bl_b + byoff, bfg[1][j]);
            }
            #pragma unroll
            for (int mt = 0; mt < 2; mt++)
                #pragma unroll
                for (int j = 0; j < 4; j++)
                    #pragma unroll
                    for (int h = 0; h < 2; h++) {
                        int nt = j * 2 + h;
                        mma16816(acc[mt][nt], af[0][mt], &bfg[0][j][h * 2]);
                        mma16816(acc[mt][nt], af[0][mt], &bfg[1][j][h * 2]);
                        mma16816(acc[mt][nt], af[1][mt], &bfg[0][j][h * 2]);
                    }
        }

        if (c < 3) {
            store_a(buf ^ 1);
            CP_WAIT0();
        }
        __syncthreads();
    }

    // ---- epilogue: hs = dinv[row] * (acc + bias) ----
    const int g4 = lane >> 2;
    const int ti = lane & 3;
    #pragma unroll
    for (int mt = 0; mt < 2; mt++) {
        int r0 = rowBase + wm * 32 + mt * 16 + g4;
        int r1 = r0 + 8;
        float d0 = (r0 < NND) ? g_dinv[r0] : 0.f;
        float d1 = (r1 < NND) ? g_dinv[r1] : 0.f;
        #pragma unroll
        for (int nt = 0; nt < 8; nt++) {
            int col = wn * 64 + nt * 8 + ti * 2;
            float b0 = bias[col], b1 = bias[col + 1];
            if (r0 < NND) {
                float2 o = make_float2((acc[mt][nt][0] + b0) * d0,
                                       (acc[mt][nt][1] + b1) * d0);
                *(float2*)(g_h + (size_t)r0 * OD + col) = o;
            }
            if (r1 < NND) {
                float2 o = make_float2((acc[mt][nt][2] + b0) * d1,
                                       (acc[mt][nt][3] + b1) * d1);
                *(float2*)(g_h + (size_t)r1 * OD + col) = o;
            }
        }
    }
}

// ---------------- CSR aggregation: warp per node, unroll 4, fused ReLU ---
__global__ __launch_bounds__(256) void agg_kernel(float* __restrict__ out) {
    int gid = blockIdx.x * 256 + threadIdx.x;
    int node = gid >> 5;
    if (node >= NND) return;
    int lane = threadIdx.x & 31;
    const float* hp = g_h + (size_t)lane * 4;

    float4 acc = *(const float4*)(hp + (size_t)node * OD);

    int s = g_start[node];
    int e = s + g_deg[node];
    int i = s;
    for (; i + 4 <= e; i += 4) {
        int r0 = g_srt[i];
        int r1 = g_srt[i + 1];
        int r2 = g_srt[i + 2];
        int r3 = g_srt[i + 3];
        float4 v0 = *(const float4*)(hp + (size_t)r0 * OD);
        float4 v1 = *(const float4*)(hp + (size_t)r1 * OD);
        float4 v2 = *(const float4*)(hp + (size_t)r2 * OD);
        float4 v3 = *(const float4*)(hp + (size_t)r3 * OD);
        acc.x += (v0.x + v1.x) + (v2.x + v3.x);
        acc.y += (v0.y + v1.y) + (v2.y + v3.y);
        acc.z += (v0.z + v1.z) + (v2.z + v3.z);
        acc.w += (v0.w + v1.w) + (v2.w + v3.w);
    }
    for (; i < e; i++) {
        int r0 = g_srt[i];
        float4 v0 = *(const float4*)(hp + (size_t)r0 * OD);
        acc.x += v0.x; acc.y += v0.y; acc.z += v0.z; acc.w += v0.w;
    }

    float d = g_dinv[node];
    float4 o;
    o.x = fmaxf(acc.x * d, 0.f);
    o.y = fmaxf(acc.y * d, 0.f);
    o.z = fmaxf(acc.z * d, 0.f);
    o.w = fmaxf(acc.w * d, 0.f);
    *(float4*)(out + (size_t)node * OD + lane * 4) = o;
}

// ---------------- launch ----------------
extern "C" void kernel_launch(void* const* d_in, const int* in_sizes, int n_in,
                              void* d_out, int out_size) {
    const float* x  = (const float*)d_in[0];
    const void*  ei = d_in[1];
    const float* W  = (const float*)d_in[2];
    const float* b  = (const float*)d_in[3];
    float* out = (float*)d_out;

    cudaFuncSetAttribute(gemm_mma_kernel,
                         cudaFuncAttributeMaxDynamicSharedMemorySize, SMEM_DYN);

    zero_detect_kernel<<<(NND + 255) / 256, 256>>>(ei);
    conv_deg_kernel<<<(NE + 255) / 256, 256>>>(ei);
    dinv_kernel<<<(NND + 255) / 256, 256>>>();
    scan_kernel<<<1, 1024>>>();
    fill_kernel<<<(NE + 255) / 256, 256>>>();
    wsplit_kernel<<<(KF * OD + 255) / 256, 256>>>(W);
    gemm_mma_kernel<<<(NND + 127) / 128, 256, SMEM_DYN>>>(x, b);
    agg_kernel<<<(NND * 32 + 255) / 256, 256>>>(out);
}

// round 6
// speedup vs baseline: 2.2810x; 1.4645x over previous
#include <cuda_runtime.h>
#include <cuda_bf16.h>
#include <cstdint>

#define NND 100000
#define NE  1600000
#define KF  256
#define OD  128
#define NBLK 98                     // ceil(NND/1024)

// ---------------- device scratch (no allocations allowed) ----------------
__device__ int   g_is64;
__device__ int   g_row[NE];
__device__ int   g_col[NE];
__device__ int   g_srt[NE];
__device__ int   g_deg[NND];
__device__ int   g_start[NND];
__device__ int   g_pos[NND];
__device__ int   g_blk[128];
__device__ int   g_blkoff[128];
__device__ float g_dinv[NND];
__device__ float g_h[(size_t)NND * OD];
__device__ __nv_bfloat16 g_wt_hi[OD * KF];
__device__ __nv_bfloat16 g_wt_lo[OD * KF];

__device__ __forceinline__ uint32_t smem_u32(const void* p) {
    uint32_t a;
    asm("{ .reg .u64 t; cvta.to.shared.u64 t, %1; cvt.u32.u64 %0, t; }"
        : "=r"(a) : "l"(p));
    return a;
}

#define CP_ASYNC16(dst, src) \
    asm volatile("cp.async.cg.shared.global [%0], [%1], 16;" \
                 :: "r"(dst), "l"(src) : "memory")
#define CP_COMMIT() asm volatile("cp.async.commit_group;" ::: "memory")
#define CP_WAIT0()  asm volatile("cp.async.wait_group 0;" ::: "memory")

// ---------------- zero + dtype detect (fused) ----------------------------
__global__ void zero_detect_kernel(const void* ei) {
    int i = blockIdx.x * blockDim.x + threadIdx.x;
    if (i < NND) { g_deg[i] = 0; g_pos[i] = 0; }
    if (i == 0) {
        const long long* p = (const long long*)ei;
        int ok64 = 1;
        #pragma unroll
        for (int j = 0; j < 16; j++) {
            long long v = p[j];
            if (v < 0 || v >= NND) ok64 = 0;
        }
        g_is64 = ok64;
    }
}

// ---------------- convert edges + degree count (fused) -------------------
__global__ void conv_deg_kernel(const void* ei) {
    int e = blockIdx.x * blockDim.x + threadIdx.x;
    if (e >= NE) return;
    int r, c;
    if (g_is64) {
        const long long* p = (const long long*)ei;
        r = (int)p[e];
        c = (int)p[e + NE];
    } else {
        const int* p = (const int*)ei;
        r = p[e];
        c = p[e + NE];
    }
    g_row[e] = r;
    g_col[e] = c;
    atomicAdd(&g_deg[c], 1);
}

// ---------------- device-wide exclusive scan (3 phases) ------------------
__global__ __launch_bounds__(1024) void scan1_kernel() {
    __shared__ int wsum[32];
    int i = blockIdx.x * 1024 + threadIdx.x;
    int lane = threadIdx.x & 31;
    int w = threadIdx.x >> 5;
    int v = (i < NND) ? g_deg[i] : 0;
    int s = v;
    #pragma unroll
    for (int o = 1; o < 32; o <<= 1) {
        int t = __shfl_up_sync(0xffffffffu, s, o);
        if (lane >= o) s += t;
    }
    if (lane == 31) wsum[w] = s;
    __syncthreads();
    if (w == 0) {
        int ws = wsum[lane];
        #pragma unroll
        for (int o = 1; o < 32; o <<= 1) {
            int t = __shfl_up_sync(0xffffffffu, ws, o);
            if (lane >= o) ws += t;
        }
        wsum[lane] = ws;
    }
    __syncthreads();
    int excl = s - v + (w > 0 ? wsum[w - 1] : 0);
    if (i < NND) g_start[i] = excl;
    if (threadIdx.x == 1023) g_blk[blockIdx.x] = excl + v;
}

__global__ __launch_bounds__(128) void scan2_kernel() {
    __shared__ int sh[128];
    int t = threadIdx.x;
    int v = (t < NBLK) ? g_blk[t] : 0;
    sh[t] = v;
    __syncthreads();
    for (int o = 1; o < 128; o <<= 1) {
        int x = (t >= o) ? sh[t - o] : 0;
        __syncthreads();
        sh[t] += x;
        __syncthreads();
    }
    if (t < NBLK) g_blkoff[t] = sh[t] - v;
}

// phase 3 + dinv fused
__global__ void scan3_kernel() {
    int i = blockIdx.x * blockDim.x + threadIdx.x;
    if (i < NND) {
        g_start[i] += g_blkoff[i >> 10];
        g_dinv[i] = rsqrtf((float)(g_deg[i] + 1));
    }
}

// ---------------- CSR fill (counting sort by destination) ----------------
__global__ void fill_kernel() {
    int e = blockIdx.x * blockDim.x + threadIdx.x;
    if (e >= NE) return;
    int c = g_col[e];
    int pos = g_start[c] + atomicAdd(&g_pos[c], 1);
    g_srt[pos] = g_row[e];
}

// ---------------- W transpose + bf16 hi/lo split -------------------------
__global__ void wsplit_kernel(const float* __restrict__ W) {
    int idx = blockIdx.x * blockDim.x + threadIdx.x;
    if (idx >= KF * OD) return;
    int k = idx >> 7;
    int n = idx & 127;
    float v = W[idx];
    __nv_bfloat16 h = __float2bfloat16_rn(v);
    __nv_bfloat16 l = __float2bfloat16_rn(v - __bfloat162float(h));
    g_wt_hi[n * KF + k] = h;
    g_wt_lo[n * KF + k] = l;
}

// ================= GEMM via mma.sync bf16, double-buffered ==============
static constexpr int SA = 72;
static constexpr int TILE_ELEMS = 128 * SA;
static constexpr int SMEM_DYN = 8 * TILE_ELEMS * 2;   // 147456 B

__device__ __forceinline__ unsigned pack_bf16x2(__nv_bfloat16 a, __nv_bfloat16 b) {
    return (unsigned)__bfloat16_as_ushort(a) | ((unsigned)__bfloat16_as_ushort(b) << 16);
}

__device__ __forceinline__ void ldmx4(uint32_t addr, uint32_t* r) {
    asm volatile("ldmatrix.sync.aligned.m8n8.x4.shared.b16 {%0,%1,%2,%3}, [%4];"
                 : "=r"(r[0]), "=r"(r[1]), "=r"(r[2]), "=r"(r[3]) : "r"(addr));
}

__device__ __forceinline__ void mma16816(float* d, const uint32_t* a,
                                         const uint32_t* b) {
    asm volatile(
        "mma.sync.aligned.m16n8k16.row.col.f32.bf16.bf16.f32 "
        "{%0,%1,%2,%3}, {%4,%5,%6,%7}, {%8,%9}, {%0,%1,%2,%3};"
        : "+f"(d[0]), "+f"(d[1]), "+f"(d[2]), "+f"(d[3])
        : "r"(a[0]), "r"(a[1]), "r"(a[2]), "r"(a[3]), "r"(b[0]), "r"(b[1]));
}

__global__ __launch_bounds__(256) void gemm_mma_kernel(
    const float* __restrict__ x, const float* __restrict__ bias)
{
    extern __shared__ __nv_bfloat16 sm[];
    __nv_bfloat16* sAh[2] = { sm,                  sm + 2 * TILE_ELEMS };
    __nv_bfloat16* sAl[2] = { sm + TILE_ELEMS,     sm + 3 * TILE_ELEMS };
    __nv_bfloat16* sBh[2] = { sm + 4 * TILE_ELEMS, sm + 6 * TILE_ELEMS };
    __nv_bfloat16* sBl[2] = { sm + 5 * TILE_ELEMS, sm + 7 * TILE_ELEMS };

    const int tid = threadIdx.x;
    const int wid = tid >> 5;
    const int lane = tid & 31;
    const int wm = wid & 3;
    const int wn = wid >> 2;
    const int rowBase = blockIdx.x * 128;

    float acc[2][8][4];
    #pragma unroll
    for (int i = 0; i < 2; i++)
        #pragma unroll
        for (int j = 0; j < 8; j++)
            #pragma unroll
            for (int q = 0; q < 4; q++) acc[i][j][q] = 0.f;

    const int a_row_off = (lane & 7) + ((lane >> 3) & 1) * 8;
    const int a_col_off = ((lane >> 4) & 1) * 8;
    const int b_n_off   = (lane & 7) + ((lane >> 4) & 1) * 8;
    const int b_k_off   = ((lane >> 3) & 1) * 8;

    float4 areg[8];

    auto load_a = [&](int k0) {
        #pragma unroll
        for (int i = 0; i < 8; i++) {
            int g = tid + i * 256;
            int r = g >> 4;
            int f4 = g & 15;
            int grow = rowBase + r;
            areg[i] = make_float4(0.f, 0.f, 0.f, 0.f);
            if (grow < NND)
                areg[i] = *(const float4*)(x + (size_t)grow * KF + k0 + f4 * 4);
        }
    };
    auto store_a = [&](int buf) {
        #pragma unroll
        for (int i = 0; i < 8; i++) {
            int g = tid + i * 256;
            int r = g >> 4;
            int f4 = g & 15;
            float4 v = areg[i];
            __nv_bfloat16 hx = __float2bfloat16_rn(v.x);
            __nv_bfloat16 hy = __float2bfloat16_rn(v.y);
            __nv_bfloat16 hz = __float2bfloat16_rn(v.z);
            __nv_bfloat16 hw = __float2bfloat16_rn(v.w);
            __nv_bfloat16 lx = __float2bfloat16_rn(v.x - __bfloat162float(hx));
            __nv_bfloat16 ly = __float2bfloat16_rn(v.y - __bfloat162float(hy));
            __nv_bfloat16 lz = __float2bfloat16_rn(v.z - __bfloat162float(hz));
            __nv_bfloat16 lw = __float2bfloat16_rn(v.w - __bfloat162float(hw));
            int off = r * SA + f4 * 4;
            *(uint2*)(sAh[buf] + off) = make_uint2(pack_bf16x2(hx, hy), pack_bf16x2(hz, hw));
            *(uint2*)(sAl[buf] + off) = make_uint2(pack_bf16x2(lx, ly), pack_bf16x2(lz, lw));
        }
    };
    auto issue_b = [&](int k0, int buf) {
        uint32_t bh = smem_u32(sBh[buf]);
        uint32_t bl = smem_u32(sBl[buf]);
        #pragma unroll
        for (int i = 0; i < 4; i++) {
            int g = tid + i * 256;
            int n = g >> 3;
            int f8 = g & 7;
            uint32_t doff = (uint32_t)(n * SA + f8 * 8) * 2;
            const __nv_bfloat16* srch = g_wt_hi + (size_t)n * KF + k0 + f8 * 8;
            const __nv_bfloat16* srcl = g_wt_lo + (size_t)n * KF + k0 + f8 * 8;
            CP_ASYNC16(bh + doff, srch);
            CP_ASYNC16(bl + doff, srcl);
        }
        CP_COMMIT();
    };

    load_a(0);
    issue_b(0, 0);
    store_a(0);
    CP_WAIT0();
    __syncthreads();

    for (int c = 0; c < 4; c++) {
        const int buf = c & 1;
        if (c < 3) {
            issue_b((c + 1) * 64, buf ^ 1);
            load_a((c + 1) * 64);
        }

        const uint32_t ah_b = smem_u32(sAh[buf]);
        const uint32_t al_b = smem_u32(sAl[buf]);
        const uint32_t bh_b = smem_u32(sBh[buf]);
        const uint32_t bl_b = smem_u32(sBl[buf]);

        #pragma unroll
        for (int ks = 0; ks < 4; ks++) {
            const int k = ks * 16;
            uint32_t af[2][2][4];
            #pragma unroll
            for (int mt = 0; mt < 2; mt++) {
                int row = wm * 32 + mt * 16 + a_row_off;
                uint32_t byoff = (uint32_t)(row * SA + k + a_col_off) * 2;
                ldmx4(ah_b + byoff, af[0][mt]);
                ldmx4(al_b + byoff, af[1][mt]);
            }
            uint32_t bfg[2][4][4];
            #pragma unroll
            for (int j = 0; j < 4; j++) {
                int n = wn * 64 + j * 16 + b_n_off;
                uint32_t byoff = (uint32_t)(n * SA + k + b_k_off) * 2;
                ldmx4(bh_b + byoff, bfg[0][j]);
                ldmx4(bl_b + byoff, bfg[1][j]);
            }
            #pragma unroll
            for (int mt = 0; mt < 2; mt++)
                #pragma unroll
                for (int j = 0; j < 4; j++)
                    #pragma unroll
                    for (int h = 0; h < 2; h++) {
                        int nt = j * 2 + h;
                        mma16816(acc[mt][nt], af[0][mt], &bfg[0][j][h * 2]);
                        mma16816(acc[mt][nt], af[0][mt], &bfg[1][j][h * 2]);
                        mma16816(acc[mt][nt], af[1][mt], &bfg[0][j][h * 2]);
                    }
        }

        if (c < 3) {
            store_a(buf ^ 1);
            CP_WAIT0();
        }
        __syncthreads();
    }

    const int g4 = lane >> 2;
    const int ti = lane & 3;
    #pragma unroll
    for (int mt = 0; mt < 2; mt++) {
        int r0 = rowBase + wm * 32 + mt * 16 + g4;
        int r1 = r0 + 8;
        float d0 = (r0 < NND) ? g_dinv[r0] : 0.f;
        float d1 = (r1 < NND) ? g_dinv[r1] : 0.f;
        #pragma unroll
        for (int nt = 0; nt < 8; nt++) {
            int col = wn * 64 + nt * 8 + ti * 2;
            float b0 = bias[col], b1 = bias[col + 1];
            if (r0 < NND) {
                float2 o = make_float2((acc[mt][nt][0] + b0) * d0,
                                       (acc[mt][nt][1] + b1) * d0);
                *(float2*)(g_h + (size_t)r0 * OD + col) = o;
            }
            if (r1 < NND) {
                float2 o = make_float2((acc[mt][nt][2] + b0) * d1,
                                       (acc[mt][nt][3] + b1) * d1);
                *(float2*)(g_h + (size_t)r1 * OD + col) = o;
            }
        }
    }
}

// ---------------- CSR aggregation: warp per node, unroll 4, fused ReLU ---
__global__ __launch_bounds__(256) void agg_kernel(float* __restrict__ out) {
    int gid = blockIdx.x * 256 + threadIdx.x;
    int node = gid >> 5;
    if (node >= NND) return;
    int lane = threadIdx.x & 31;
    const float* hp = g_h + (size_t)lane * 4;

    float4 acc = *(const float4*)(hp + (size_t)node * OD);

    int s = g_start[node];
    int e = s + g_deg[node];
    int i = s;
    for (; i + 4 <= e; i += 4) {
        int r0 = g_srt[i];
        int r1 = g_srt[i + 1];
        int r2 = g_srt[i + 2];
        int r3 = g_srt[i + 3];
        float4 v0 = *(const float4*)(hp + (size_t)r0 * OD);
        float4 v1 = *(const float4*)(hp + (size_t)r1 * OD);
        float4 v2 = *(const float4*)(hp + (size_t)r2 * OD);
        float4 v3 = *(const float4*)(hp + (size_t)r3 * OD);
        acc.x += (v0.x + v1.x) + (v2.x + v3.x);
        acc.y += (v0.y + v1.y) + (v2.y + v3.y);
        acc.z += (v0.z + v1.z) + (v2.z + v3.z);
        acc.w += (v0.w + v1.w) + (v2.w + v3.w);
    }
    for (; i < e; i++) {
        int r0 = g_srt[i];
        float4 v0 = *(const float4*)(hp + (size_t)r0 * OD);
        acc.x += v0.x; acc.y += v0.y; acc.z += v0.z; acc.w += v0.w;
    }

    float d = g_dinv[node];
    float4 o;
    o.x = fmaxf(acc.x * d, 0.f);
    o.y = fmaxf(acc.y * d, 0.f);
    o.z = fmaxf(acc.z * d, 0.f);
    o.w = fmaxf(acc.w * d, 0.f);
    *(float4*)(out + (size_t)node * OD + lane * 4) = o;
}

// ---------------- launch ----------------
extern "C" void kernel_launch(void* const* d_in, const int* in_sizes, int n_in,
                              void* d_out, int out_size) {
    const float* x  = (const float*)d_in[0];
    const void*  ei = d_in[1];
    const float* W  = (const float*)d_in[2];
    const float* b  = (const float*)d_in[3];
    float* out = (float*)d_out;

    cudaFuncSetAttribute(gemm_mma_kernel,
                         cudaFuncAttributeMaxDynamicSharedMemorySize, SMEM_DYN);

    zero_detect_kernel<<<(NND + 255) / 256, 256>>>(ei);
    conv_deg_kernel<<<(NE + 255) / 256, 256>>>(ei);
    scan1_kernel<<<NBLK, 1024>>>();
    scan2_kernel<<<1, 128>>>();
    scan3_kernel<<<(NND + 255) / 256, 256>>>();
    fill_kernel<<<(NE + 255) / 256, 256>>>();
    wsplit_kernel<<<(KF * OD + 255) / 256, 256>>>(W);
    gemm_mma_kernel<<<(NND + 127) / 128, 256, SMEM_DYN>>>(x, b);
    agg_kernel<<<(NND * 32 + 255) / 256, 256>>>(out);
}

// round 8
// speedup vs baseline: 2.4082x; 1.0558x over previous
#include <cuda_runtime.h>
#include <cuda_bf16.h>
#include <cuda_fp16.h>
#include <cstdint>

#define NND 100000
#define NE  1600000
#define KF  256
#define OD  128

// ---------------- device scratch (no allocations allowed) ----------------
__device__ int   g_is64;
__device__ int   g_total;
__device__ int   g_row[NE];
__device__ int   g_col[NE];
__device__ int   g_srt[NE];
__device__ int   g_deg[NND];
__device__ int   g_start[NND];
__device__ int   g_pos[NND];
__device__ float g_dinv[NND];
__device__ __half g_hb[(size_t)NND * OD];           // h scaled, fp16, 25.6 MB
__device__ __nv_bfloat16 g_wt_hi[OD * KF];
__device__ __nv_bfloat16 g_wt_lo[OD * KF];

__device__ __forceinline__ uint32_t smem_u32(const void* p) {
    uint32_t a;
    asm("{ .reg .u64 t; cvta.to.shared.u64 t, %1; cvt.u32.u64 %0, t; }"
        : "=r"(a) : "l"(p));
    return a;
}

#define CP_ASYNC16(dst, src) \
    asm volatile("cp.async.cg.shared.global [%0], [%1], 16;" \
                 :: "r"(dst), "l"(src) : "memory")
#define CP_COMMIT() asm volatile("cp.async.commit_group;" ::: "memory")
#define CP_WAIT0()  asm volatile("cp.async.wait_group 0;" ::: "memory")

// ---------------- zero + dtype detect (fused) ----------------------------
__global__ void zero_detect_kernel(const void* ei) {
    int i = blockIdx.x * blockDim.x + threadIdx.x;
    if (i < NND) { g_deg[i] = 0; g_pos[i] = 0; }
    if (i == 0) {
        g_total = 0;
        const long long* p = (const long long*)ei;
        int ok64 = 1;
        #pragma unroll
        for (int j = 0; j < 16; j++) {
            long long v = p[j];
            if (v < 0 || v >= NND) ok64 = 0;
        }
        g_is64 = ok64;
    }
}

// ---------------- convert edges + degree count (fused) -------------------
__global__ void conv_deg_kernel(const void* ei) {
    int e = blockIdx.x * blockDim.x + threadIdx.x;
    if (e >= NE) return;
    int r, c;
    if (g_is64) {
        const long long* p = (const long long*)ei;
        r = (int)p[e];
        c = (int)p[e + NE];
    } else {
        const int* p = (const int*)ei;
        r = p[e];
        c = p[e + NE];
    }
    g_row[e] = r;
    g_col[e] = c;
    atomicAdd(&g_deg[c], 1);
}

// ---------------- offset assign (warp-aggregated atomic) + dinv ----------
__global__ void offset_dinv_kernel() {
    int i = blockIdx.x * blockDim.x + threadIdx.x;
    int lane = threadIdx.x & 31;
    int deg = (i < NND) ? g_deg[i] : 0;
    int s = deg;
    #pragma unroll
    for (int o = 1; o < 32; o <<= 1) {
        int t = __shfl_up_sync(0xffffffffu, s, o);
        if (lane >= o) s += t;
    }
    int total = __shfl_sync(0xffffffffu, s, 31);
    int base = 0;
    if (lane == 0) base = atomicAdd(&g_total, total);
    base = __shfl_sync(0xffffffffu, base, 0);
    if (i < NND) {
        g_start[i] = base + s - deg;
        g_dinv[i] = rsqrtf((float)(deg + 1));
    }
}

// ---------------- CSR fill (counting sort by destination) ----------------
__global__ void fill_kernel() {
    int e = blockIdx.x * blockDim.x + threadIdx.x;
    if (e >= NE) return;
    int c = g_col[e];
    int pos = g_start[c] + atomicAdd(&g_pos[c], 1);
    g_srt[pos] = g_row[e];
}

// ---------------- W transpose + bf16 hi/lo split -------------------------
__global__ void wsplit_kernel(const float* __restrict__ W) {
    int idx = blockIdx.x * blockDim.x + threadIdx.x;
    if (idx >= KF * OD) return;
    int k = idx >> 7;
    int n = idx & 127;
    float v = W[idx];
    __nv_bfloat16 h = __float2bfloat16_rn(v);
    __nv_bfloat16 l = __float2bfloat16_rn(v - __bfloat162float(h));
    g_wt_hi[n * KF + k] = h;
    g_wt_lo[n * KF + k] = l;
}

// ================= GEMM via mma.sync bf16, double-buffered ==============
static constexpr int SA = 72;
static constexpr int TILE_ELEMS = 128 * SA;
static constexpr int SMEM_DYN = 8 * TILE_ELEMS * 2;   // 147456 B

__device__ __forceinline__ unsigned pack_bf16x2(__nv_bfloat16 a, __nv_bfloat16 b) {
    return (unsigned)__bfloat16_as_ushort(a) | ((unsigned)__bfloat16_as_ushort(b) << 16);
}
__device__ __forceinline__ unsigned pack_h2(float a, float b) {
    __half2 h = __floats2half2_rn(a, b);
    return *(unsigned*)&h;
}

__device__ __forceinline__ void ldmx4(uint32_t addr, uint32_t* r) {
    asm volatile("ldmatrix.sync.aligned.m8n8.x4.shared.b16 {%0,%1,%2,%3}, [%4];"
                 : "=r"(r[0]), "=r"(r[1]), "=r"(r[2]), "=r"(r[3]) : "r"(addr));
}

__device__ __forceinline__ void mma16816(float* d, const uint32_t* a,
                                         const uint32_t* b) {
    asm volatile(
        "mma.sync.aligned.m16n8k16.row.col.f32.bf16.bf16.f32 "
        "{%0,%1,%2,%3}, {%4,%5,%6,%7}, {%8,%9}, {%0,%1,%2,%3};"
        : "+f"(d[0]), "+f"(d[1]), "+f"(d[2]), "+f"(d[3])
        : "r"(a[0]), "r"(a[1]), "r"(a[2]), "r"(a[3]), "r"(b[0]), "r"(b[1]));
}

__global__ __launch_bounds__(256) void gemm_mma_kernel(
    const float* __restrict__ x, const float* __restrict__ bias)
{
    extern __shared__ __nv_bfloat16 sm[];
    __nv_bfloat16* sAh[2] = { sm,                  sm + 2 * TILE_ELEMS };
    __nv_bfloat16* sAl[2] = { sm + TILE_ELEMS,     sm + 3 * TILE_ELEMS };
    __nv_bfloat16* sBh[2] = { sm + 4 * TILE_ELEMS, sm + 6 * TILE_ELEMS };
    __nv_bfloat16* sBl[2] = { sm + 5 * TILE_ELEMS, sm + 7 * TILE_ELEMS };

    const int tid = threadIdx.x;
    const int wid = tid >> 5;
    const int lane = tid & 31;
    const int wm = wid & 3;
    const int wn = wid >> 2;
    const int rowBase = blockIdx.x * 128;

    float acc[2][8][4];
    #pragma unroll
    for (int i = 0; i < 2; i++)
        #pragma unroll
        for (int j = 0; j < 8; j++)
            #pragma unroll
            for (int q = 0; q < 4; q++) acc[i][j][q] = 0.f;

    const int a_row_off = (lane & 7) + ((lane >> 3) & 1) * 8;
    const int a_col_off = ((lane >> 4) & 1) * 8;
    const int b_n_off   = (lane & 7) + ((lane >> 4) & 1) * 8;
    const int b_k_off   = ((lane >> 3) & 1) * 8;

    float4 areg[8];

    auto load_a = [&](int k0) {
        #pragma unroll
        for (int i = 0; i < 8; i++) {
            int g = tid + i * 256;
            int r = g >> 4;
            int f4 = g & 15;
            int grow = rowBase + r;
            areg[i] = make_float4(0.f, 0.f, 0.f, 0.f);
            if (grow < NND)
                areg[i] = *(const float4*)(x + (size_t)grow * KF + k0 + f4 * 4);
        }
    };
    auto store_a = [&](int buf) {
        #pragma unroll
        for (int i = 0; i < 8; i++) {
            int g = tid + i * 256;
            int r = g >> 4;
            int f4 = g & 15;
            float4 v = areg[i];
            __nv_bfloat16 hx = __float2bfloat16_rn(v.x);
            __nv_bfloat16 hy = __float2bfloat16_rn(v.y);
            __nv_bfloat16 hz = __float2bfloat16_rn(v.z);
            __nv_bfloat16 hw = __float2bfloat16_rn(v.w);
            __nv_bfloat16 lx = __float2bfloat16_rn(v.x - __bfloat162float(hx));
            __nv_bfloat16 ly = __float2bfloat16_rn(v.y - __bfloat162float(hy));
            __nv_bfloat16 lz = __float2bfloat16_rn(v.z - __bfloat162float(hz));
            __nv_bfloat16 lw = __float2bfloat16_rn(v.w - __bfloat162float(hw));
            int off = r * SA + f4 * 4;
            *(uint2*)(sAh[buf] + off) = make_uint2(pack_bf16x2(hx, hy), pack_bf16x2(hz, hw));
            *(uint2*)(sAl[buf] + off) = make_uint2(pack_bf16x2(lx, ly), pack_bf16x2(lz, lw));
        }
    };
    auto issue_b = [&](int k0, int buf) {
        uint32_t bh = smem_u32(sBh[buf]);
        uint32_t bl = smem_u32(sBl[buf]);
        #pragma unroll
        for (int i = 0; i < 4; i++) {
            int g = tid + i * 256;
            int n = g >> 3;
            int f8 = g & 7;
            uint32_t doff = (uint32_t)(n * SA + f8 * 8) * 2;
            const __nv_bfloat16* srch = g_wt_hi + (size_t)n * KF + k0 + f8 * 8;
            const __nv_bfloat16* srcl = g_wt_lo + (size_t)n * KF + k0 + f8 * 8;
            CP_ASYNC16(bh + doff, srch);
            CP_ASYNC16(bl + doff, srcl);
        }
        CP_COMMIT();
    };

    load_a(0);
    issue_b(0, 0);
    store_a(0);
    CP_WAIT0();
    __syncthreads();

    for (int c = 0; c < 4; c++) {
        const int buf = c & 1;
        if (c < 3) {
            issue_b((c + 1) * 64, buf ^ 1);
            load_a((c + 1) * 64);
        }

        const uint32_t ah_b = smem_u32(sAh[buf]);
        const uint32_t al_b = smem_u32(sAl[buf]);
        const uint32_t bh_b = smem_u32(sBh[buf]);
        const uint32_t bl_b = smem_u32(sBl[buf]);

        #pragma unroll
        for (int ks = 0; ks < 4; ks++) {
            const int k = ks * 16;
            uint32_t af[2][2][4];
            #pragma unroll
            for (int mt = 0; mt < 2; mt++) {
                int row = wm * 32 + mt * 16 + a_row_off;
                uint32_t byoff = (uint32_t)(row * SA + k + a_col_off) * 2;
                ldmx4(ah_b + byoff, af[0][mt]);
                ldmx4(al_b + byoff, af[1][mt]);
            }
            uint32_t bfg[2][4][4];
            #pragma unroll
            for (int j = 0; j < 4; j++) {
                int n = wn * 64 + j * 16 + b_n_off;
                uint32_t byoff = (uint32_t)(n * SA + k + b_k_off) * 2;
                ldmx4(bh_b + byoff, bfg[0][j]);
                ldmx4(bl_b + byoff, bfg[1][j]);
            }
            #pragma unroll
            for (int mt = 0; mt < 2; mt++)
                #pragma unroll
                for (int j = 0; j < 4; j++)
                    #pragma unroll
                    for (int h = 0; h < 2; h++) {
                        int nt = j * 2 + h;
                        mma16816(acc[mt][nt], af[0][mt], &bfg[0][j][h * 2]);
                        mma16816(acc[mt][nt], af[0][mt], &bfg[1][j][h * 2]);
                        mma16816(acc[mt][nt], af[1][mt], &bfg[0][j][h * 2]);
                    }
        }

        if (c < 3) {
            store_a(buf ^ 1);
            CP_WAIT0();
        }
        __syncthreads();
    }

    // ---- epilogue: hb = fp16( dinv[row] * (acc + bias) ) ----
    const int g4 = lane >> 2;
    const int ti = lane & 3;
    #pragma unroll
    for (int mt = 0; mt < 2; mt++) {
        int r0 = rowBase + wm * 32 + mt * 16 + g4;
        int r1 = r0 + 8;
        float d0 = (r0 < NND) ? g_dinv[r0] : 0.f;
        float d1 = (r1 < NND) ? g_dinv[r1] : 0.f;
        #pragma unroll
        for (int nt = 0; nt < 8; nt++) {
            int col = wn * 64 + nt * 8 + ti * 2;
            float b0 = bias[col], b1 = bias[col + 1];
            if (r0 < NND) {
                unsigned v = pack_h2((acc[mt][nt][0] + b0) * d0,
                                     (acc[mt][nt][1] + b1) * d0);
                *(unsigned*)(g_hb + (size_t)r0 * OD + col) = v;
            }
            if (r1 < NND) {
                unsigned v = pack_h2((acc[mt][nt][2] + b0) * d1,
                                     (acc[mt][nt][3] + b1) * d1);
                *(unsigned*)(g_hb + (size_t)r1 * OD + col) = v;
            }
        }
    }
}

// ---------------- CSR aggregation: warp per node, fp16 gather ------------
__device__ __forceinline__ float4 h4_to_f4(uint2 v) {
    __half2 a = *(__half2*)&v.x;
    __half2 b = *(__half2*)&v.y;
    float2 fa = __half22float2(a);
    float2 fb = __half22float2(b);
    return make_float4(fa.x, fa.y, fb.x, fb.y);
}

__global__ __launch_bounds__(256) void agg_kernel(float* __restrict__ out) {
    int gid = blockIdx.x * 256 + threadIdx.x;
    int node = gid >> 5;
    if (node >= NND) return;
    int lane = threadIdx.x & 31;
    const __half* hb = g_hb + (size_t)lane * 4;

    float4 acc = h4_to_f4(*(const uint2*)(hb + (size_t)node * OD));

    int s = g_start[node];
    int e = s + g_deg[node];
    int i = s;
    for (; i + 4 <= e; i += 4) {
        int r0 = g_srt[i];
        int r1 = g_srt[i + 1];
        int r2 = g_srt[i + 2];
        int r3 = g_srt[i + 3];
        uint2 u0 = *(const uint2*)(hb + (size_t)r0 * OD);
        uint2 u1 = *(const uint2*)(hb + (size_t)r1 * OD);
        uint2 u2 = *(const uint2*)(hb + (size_t)r2 * OD);
        uint2 u3 = *(const uint2*)(hb + (size_t)r3 * OD);
        float4 v0 = h4_to_f4(u0);
        float4 v1 = h4_to_f4(u1);
        float4 v2 = h4_to_f4(u2);
        float4 v3 = h4_to_f4(u3);
        acc.x += (v0.x + v1.x) + (v2.x + v3.x);
        acc.y += (v0.y + v1.y) + (v2.y + v3.y);
        acc.z += (v0.z + v1.z) + (v2.z + v3.z);
        acc.w += (v0.w + v1.w) + (v2.w + v3.w);
    }
    for (; i < e; i++) {
        int r0 = g_srt[i];
        float4 v0 = h4_to_f4(*(const uint2*)(hb + (size_t)r0 * OD));
        acc.x += v0.x; acc.y += v0.y; acc.z += v0.z; acc.w += v0.w;
    }

    float d = g_dinv[node];
    float4 o;
    o.x = fmaxf(acc.x * d, 0.f);
    o.y = fmaxf(acc.y * d, 0.f);
    o.z = fmaxf(acc.z * d, 0.f);
    o.w = fmaxf(acc.w * d, 0.f);
    *(float4*)(out + (size_t)node * OD + lane * 4) = o;
}

// ---------------- launch ----------------
extern "C" void kernel_launch(void* const* d_in, const int* in_sizes, int n_in,
                              void* d_out, int out_size) {
    const float* x  = (const float*)d_in[0];
    const void*  ei = d_in[1];
    const float* W  = (const float*)d_in[2];
    const float* b  = (const float*)d_in[3];
    float* out = (float*)d_out;

    cudaFuncSetAttribute(gemm_mma_kernel,
                         cudaFuncAttributeMaxDynamicSharedMemorySize, SMEM_DYN);

    zero_detect_kernel<<<(NND + 255) / 256, 256>>>(ei);
    conv_deg_kernel<<<(NE + 255) / 256, 256>>>(ei);
    offset_dinv_kernel<<<(NND + 255) / 256, 256>>>();
    fill_kernel<<<(NE + 255) / 256, 256>>>();
    wsplit_kernel<<<(KF * OD + 255) / 256, 256>>>(W);
    gemm_mma_kernel<<<(NND + 127) / 128, 256, SMEM_DYN>>>(x, b);
    agg_kernel<<<(NND * 32 + 255) / 256, 256>>>(out);
}

// round 9
// speedup vs baseline: 2.9415x; 1.2214x over previous
#include <cuda_runtime.h>
#include <cuda_bf16.h>
#include <cuda_fp16.h>
#include <cstdint>

#define NND 100000
#define NE  1600000
#define KF  256
#define OD  128

// ---------------- device scratch (no allocations allowed) ----------------
__device__ int   g_is64;
__device__ int   g_total;
__device__ int   g_row[NE];
__device__ int   g_col[NE];
__device__ int   g_rank[NE];         // arrival rank within destination bucket
__device__ int   g_srt[NE];
__device__ int   g_deg[NND];
__device__ int   g_start[NND];
__device__ float g_dinv[NND];
__device__ __half g_hb[(size_t)NND * OD];           // h scaled, fp16, 25.6 MB
__device__ __nv_bfloat16 g_wt_hi[OD * KF];
__device__ __nv_bfloat16 g_wt_lo[OD * KF];

__device__ __forceinline__ uint32_t smem_u32(const void* p) {
    uint32_t a;
    asm("{ .reg .u64 t; cvta.to.shared.u64 t, %1; cvt.u32.u64 %0, t; }"
        : "=r"(a) : "l"(p));
    return a;
}

#define CP_ASYNC16(dst, src) \
    asm volatile("cp.async.cg.shared.global [%0], [%1], 16;" \
                 :: "r"(dst), "l"(src) : "memory")
#define CP_COMMIT() asm volatile("cp.async.commit_group;" ::: "memory")
#define CP_WAIT0()  asm volatile("cp.async.wait_group 0;" ::: "memory")

// ---------------- launch 1: zero deg + dtype detect + W split ------------
__global__ void zero_wsplit_kernel(const void* ei, const float* __restrict__ W) {
    int i = blockIdx.x * blockDim.x + threadIdx.x;
    if (i < NND) g_deg[i] = 0;
    if (i == 0) {
        g_total = 0;
        const long long* p = (const long long*)ei;
        int ok64 = 1;
        #pragma unroll
        for (int j = 0; j < 16; j++) {
            long long v = p[j];
            if (v < 0 || v >= NND) ok64 = 0;
        }
        g_is64 = ok64;
    }
    if (i < KF * OD) {
        int k = i >> 7;
        int n = i & 127;
        float v = W[i];
        __nv_bfloat16 h = __float2bfloat16_rn(v);
        __nv_bfloat16 l = __float2bfloat16_rn(v - __bfloat162float(h));
        g_wt_hi[n * KF + k] = h;
        g_wt_lo[n * KF + k] = l;
    }
}

// ---------------- launch 2: convert edges + degree count + rank ----------
__global__ void conv_deg_kernel(const void* ei) {
    int e = blockIdx.x * blockDim.x + threadIdx.x;
    if (e >= NE) return;
    int r, c;
    if (g_is64) {
        const long long* p = (const long long*)ei;
        r = (int)p[e];
        c = (int)p[e + NE];
    } else {
        const int* p = (const int*)ei;
        r = p[e];
        c = p[e + NE];
    }
    g_row[e] = r;
    g_col[e] = c;
    g_rank[e] = atomicAdd(&g_deg[c], 1);
}

// ---------------- launch 3: offsets (warp-aggregated atomic) + dinv ------
__global__ void offset_dinv_kernel() {
    int i = blockIdx.x * blockDim.x + threadIdx.x;
    int lane = threadIdx.x & 31;
    int deg = (i < NND) ? g_deg[i] : 0;
    int s = deg;
    #pragma unroll
    for (int o = 1; o < 32; o <<= 1) {
        int t = __shfl_up_sync(0xffffffffu, s, o);
        if (lane >= o) s += t;
    }
    int total = __shfl_sync(0xffffffffu, s, 31);
    int base = 0;
    if (lane == 0) base = atomicAdd(&g_total, total);
    base = __shfl_sync(0xffffffffu, base, 0);
    if (i < NND) {
        g_start[i] = base + s - deg;
        g_dinv[i] = rsqrtf((float)(deg + 1));
    }
}

// ================= launch 4: GEMM (mma.sync bf16 split, 2 CTA/SM) =======
// CTA tile 64(M)x128(N), K chunks of 64. 8 warps in 2(M)x4(N) grid,
// warp tile 32x32. D = xh*Wh + xh*Wl + xl*Wh, fp32 accum.
static constexpr int SA = 72;
static constexpr int TILE_A = 64 * SA;       // 4608 elems
static constexpr int TILE_B = 128 * SA;      // 9216 elems
static constexpr int SMEM_DYN = (4 * TILE_A + 4 * TILE_B) * 2;   // 110592 B

__device__ __forceinline__ unsigned pack_bf16x2(__nv_bfloat16 a, __nv_bfloat16 b) {
    return (unsigned)__bfloat16_as_ushort(a) | ((unsigned)__bfloat16_as_ushort(b) << 16);
}
__device__ __forceinline__ unsigned pack_h2(float a, float b) {
    __half2 h = __floats2half2_rn(a, b);
    return *(unsigned*)&h;
}

__device__ __forceinline__ void ldmx4(uint32_t addr, uint32_t* r) {
    asm volatile("ldmatrix.sync.aligned.m8n8.x4.shared.b16 {%0,%1,%2,%3}, [%4];"
                 : "=r"(r[0]), "=r"(r[1]), "=r"(r[2]), "=r"(r[3]) : "r"(addr));
}

__device__ __forceinline__ void mma16816(float* d, const uint32_t* a,
                                         const uint32_t* b) {
    asm volatile(
        "mma.sync.aligned.m16n8k16.row.col.f32.bf16.bf16.f32 "
        "{%0,%1,%2,%3}, {%4,%5,%6,%7}, {%8,%9}, {%0,%1,%2,%3};"
        : "+f"(d[0]), "+f"(d[1]), "+f"(d[2]), "+f"(d[3])
        : "r"(a[0]), "r"(a[1]), "r"(a[2]), "r"(a[3]), "r"(b[0]), "r"(b[1]));
}

__global__ __launch_bounds__(256) void gemm_mma_kernel(
    const float* __restrict__ x, const float* __restrict__ bias)
{
    extern __shared__ __nv_bfloat16 sm[];
    __nv_bfloat16* sAh[2] = { sm,              sm + 2 * TILE_A };
    __nv_bfloat16* sAl[2] = { sm + TILE_A,     sm + 3 * TILE_A };
    __nv_bfloat16* base_b = sm + 4 * TILE_A;
    __nv_bfloat16* sBh[2] = { base_b,              base_b + 2 * TILE_B };
    __nv_bfloat16* sBl[2] = { base_b + TILE_B,     base_b + 3 * TILE_B };

    const int tid = threadIdx.x;
    const int wid = tid >> 5;
    const int lane = tid & 31;
    const int wm = wid & 1;           // 0..1 -> rows wm*32
    const int wn = wid >> 1;          // 0..3 -> cols wn*32
    const int rowBase = blockIdx.x * 64;

    float acc[2][4][4];
    #pragma unroll
    for (int i = 0; i < 2; i++)
        #pragma unroll
        for (int j = 0; j < 4; j++)
            #pragma unroll
            for (int q = 0; q < 4; q++) acc[i][j][q] = 0.f;

    const int a_row_off = (lane & 7) + ((lane >> 3) & 1) * 8;
    const int a_col_off = ((lane >> 4) & 1) * 8;
    const int b_n_off   = (lane & 7) + ((lane >> 4) & 1) * 8;
    const int b_k_off   = ((lane >> 3) & 1) * 8;

    float4 areg[4];

    auto load_a = [&](int k0) {
        #pragma unroll
        for (int i = 0; i < 4; i++) {
            int g = tid + i * 256;           // 0..1023
            int r = g >> 4;                  // 0..63
            int f4 = g & 15;
            int grow = rowBase + r;
            areg[i] = make_float4(0.f, 0.f, 0.f, 0.f);
            if (grow < NND)
                areg[i] = *(const float4*)(x + (size_t)grow * KF + k0 + f4 * 4);
        }
    };
    auto store_a = [&](int buf) {
        #pragma unroll
        for (int i = 0; i < 4; i++) {
            int g = tid + i * 256;
            int r = g >> 4;
            int f4 = g & 15;
            float4 v = areg[i];
            __nv_bfloat16 hx = __float2bfloat16_rn(v.x);
            __nv_bfloat16 hy = __float2bfloat16_rn(v.y);
            __nv_bfloat16 hz = __float2bfloat16_rn(v.z);
            __nv_bfloat16 hw = __float2bfloat16_rn(v.w);
            __nv_bfloat16 lx = __float2bfloat16_rn(v.x - __bfloat162float(hx));
            __nv_bfloat16 ly = __float2bfloat16_rn(v.y - __bfloat162float(hy));
            __nv_bfloat16 lz = __float2bfloat16_rn(v.z - __bfloat162float(hz));
            __nv_bfloat16 lw = __float2bfloat16_rn(v.w - __bfloat162float(hw));
            int off = r * SA + f4 * 4;
            *(uint2*)(sAh[buf] + off) = make_uint2(pack_bf16x2(hx, hy), pack_bf16x2(hz, hw));
            *(uint2*)(sAl[buf] + off) = make_uint2(pack_bf16x2(lx, ly), pack_bf16x2(lz, lw));
        }
    };
    auto issue_b = [&](int k0, int buf) {
        uint32_t bh = smem_u32(sBh[buf]);
        uint32_t bl = smem_u32(sBl[buf]);
        #pragma unroll
        for (int i = 0; i < 4; i++) {
            int g = tid + i * 256;           // 0..1023
            int n = g >> 3;                  // 0..127
            int f8 = g & 7;
            uint32_t doff = (uint32_t)(n * SA + f8 * 8) * 2;
            const __nv_bfloat16* srch = g_wt_hi + (size_t)n * KF + k0 + f8 * 8;
            const __nv_bfloat16* srcl = g_wt_lo + (size_t)n * KF + k0 + f8 * 8;
            CP_ASYNC16(bh + doff, srch);
            CP_ASYNC16(bl + doff, srcl);
        }
        CP_COMMIT();
    };

    load_a(0);
    issue_b(0, 0);
    store_a(0);
    CP_WAIT0();
    __syncthreads();

    for (int c = 0; c < 4; c++) {
        const int buf = c & 1;
        if (c < 3) {
            issue_b((c + 1) * 64, buf ^ 1);
            load_a((c + 1) * 64);
        }

        const uint32_t ah_b = smem_u32(sAh[buf]);
        const uint32_t al_b = smem_u32(sAl[buf]);
        const uint32_t bh_b = smem_u32(sBh[buf]);
        const uint32_t bl_b = smem_u32(sBl[buf]);

        #pragma unroll
        for (int ks = 0; ks < 4; ks++) {
            const int k = ks * 16;
            uint32_t af[2][2][4];            // [hi/lo][mtile][4]
            #pragma unroll
            for (int mt = 0; mt < 2; mt++) {
                int row = wm * 32 + mt * 16 + a_row_off;
                uint32_t byoff = (uint32_t)(row * SA + k + a_col_off) * 2;
                ldmx4(ah_b + byoff, af[0][mt]);
                ldmx4(al_b + byoff, af[1][mt]);
            }
            uint32_t bfg[2][2][4];           // [hi/lo][n16 group][4]
            #pragma unroll
            for (int j = 0; j < 2; j++) {
                int n = wn * 32 + j * 16 + b_n_off;
                uint32_t byoff = (uint32_t)(n * SA + k + b_k_off) * 2;
                ldmx4(bh_b + byoff, bfg[0][j]);
                ldmx4(bl_b + byoff, bfg[1][j]);
            }
            #pragma unroll
            for (int mt = 0; mt < 2; mt++)
                #pragma unroll
                for (int j = 0; j < 2; j++)
                    #pragma unroll
                    for (int h = 0; h < 2; h++) {
                        int nt = j * 2 + h;
                        mma16816(acc[mt][nt], af[0][mt], &bfg[0][j][h * 2]);
                        mma16816(acc[mt][nt], af[0][mt], &bfg[1][j][h * 2]);
                        mma16816(acc[mt][nt], af[1][mt], &bfg[0][j][h * 2]);
                    }
        }

        if (c < 3) {
            store_a(buf ^ 1);
            CP_WAIT0();
        }
        __syncthreads();
    }

    // ---- epilogue: hb = fp16( dinv[row] * (acc + bias) ) ----
    const int g4 = lane >> 2;
    const int ti = lane & 3;
    #pragma unroll
    for (int mt = 0; mt < 2; mt++) {
        int r0 = rowBase + wm * 32 + mt * 16 + g4;
        int r1 = r0 + 8;
        float d0 = (r0 < NND) ? g_dinv[r0] : 0.f;
        float d1 = (r1 < NND) ? g_dinv[r1] : 0.f;
        #pragma unroll
        for (int nt = 0; nt < 4; nt++) {
            int col = wn * 32 + nt * 8 + ti * 2;
            float b0 = bias[col], b1 = bias[col + 1];
            if (r0 < NND) {
                unsigned v = pack_h2((acc[mt][nt][0] + b0) * d0,
                                     (acc[mt][nt][1] + b1) * d0);
                *(unsigned*)(g_hb + (size_t)r0 * OD + col) = v;
            }
            if (r1 < NND) {
                unsigned v = pack_h2((acc[mt][nt][2] + b0) * d1,
                                     (acc[mt][nt][3] + b1) * d1);
                *(unsigned*)(g_hb + (size_t)r1 * OD + col) = v;
            }
        }
    }
}

// ---------------- launch 5: CSR fill (atomic-free, rank-based) -----------
__global__ void fill_kernel() {
    int e = blockIdx.x * blockDim.x + threadIdx.x;
    if (e >= NE) return;
    int c = g_col[e];
    g_srt[g_start[c] + g_rank[e]] = g_row[e];
}

// ---------------- launch 6: CSR aggregation (warp/node, fp16 gather) -----
__device__ __forceinline__ float4 h4_to_f4(uint2 v) {
    __half2 a = *(__half2*)&v.x;
    __half2 b = *(__half2*)&v.y;
    float2 fa = __half22float2(a);
    float2 fb = __half22float2(b);
    return make_float4(fa.x, fa.y, fb.x, fb.y);
}

__global__ __launch_bounds__(256) void agg_kernel(float* __restrict__ out) {
    int gid = blockIdx.x * 256 + threadIdx.x;
    int node = gid >> 5;
    if (node >= NND) return;
    int lane = threadIdx.x & 31;
    const __half* hb = g_hb + (size_t)lane * 4;

    float4 acc = h4_to_f4(*(const uint2*)(hb + (size_t)node * OD));

    int s = g_start[node];
    int e = s + g_deg[node];
    int i = s;
    for (; i + 4 <= e; i += 4) {
        int r0 = g_srt[i];
        int r1 = g_srt[i + 1];
        int r2 = g_srt[i + 2];
        int r3 = g_srt[i + 3];
        uint2 u0 = *(const uint2*)(hb + (size_t)r0 * OD);
        uint2 u1 = *(const uint2*)(hb + (size_t)r1 * OD);
        uint2 u2 = *(const uint2*)(hb + (size_t)r2 * OD);
        uint2 u3 = *(const uint2*)(hb + (size_t)r3 * OD);
        float4 v0 = h4_to_f4(u0);
        float4 v1 = h4_to_f4(u1);
        float4 v2 = h4_to_f4(u2);
        float4 v3 = h4_to_f4(u3);
        acc.x += (v0.x + v1.x) + (v2.x + v3.x);
        acc.y += (v0.y + v1.y) + (v2.y + v3.y);
        acc.z += (v0.z + v1.z) + (v2.z + v3.z);
        acc.w += (v0.w + v1.w) + (v2.w + v3.w);
    }
    for (; i < e; i++) {
        int r0 = g_srt[i];
        float4 v0 = h4_to_f4(*(const uint2*)(hb + (size_t)r0 * OD));
        acc.x += v0.x; acc.y += v0.y; acc.z += v0.z; acc.w += v0.w;
    }

    float d = g_dinv[node];
    float4 o;
    o.x = fmaxf(acc.x * d, 0.f);
    o.y = fmaxf(acc.y * d, 0.f);
    o.z = fmaxf(acc.z * d, 0.f);
    o.w = fmaxf(acc.w * d, 0.f);
    *(float4*)(out + (size_t)node * OD + lane * 4) = o;
}

// ---------------- launch ----------------
extern "C" void kernel_launch(void* const* d_in, const int* in_sizes, int n_in,
                              void* d_out, int out_size) {
    const float* x  = (const float*)d_in[0];
    const void*  ei = d_in[1];
    const float* W  = (const float*)d_in[2];
    const float* b  = (const float*)d_in[3];
    float* out = (float*)d_out;

    cudaFuncSetAttribute(gemm_mma_kernel,
                         cudaFuncAttributeMaxDynamicSharedMemorySize, SMEM_DYN);

    zero_wsplit_kernel<<<(NND + 255) / 256, 256>>>(ei, W);
    conv_deg_kernel<<<(NE + 255) / 256, 256>>>(ei);
    offset_dinv_kernel<<<(NND + 255) / 256, 256>>>();
    gemm_mma_kernel<<<(NND + 63) / 64, 256, SMEM_DYN>>>(x, b);
    fill_kernel<<<(NE + 255) / 256, 256>>>();
    agg_kernel<<<(NND * 32 + 255) / 256, 256>>>(out);
}

// round 10
// speedup vs baseline: 3.2110x; 1.0916x over previous
#include <cuda_runtime.h>
#include <cuda_bf16.h>
#include <cuda_fp16.h>
#include <cstdint>

#define NND 100000
#define NE  1600000
#define KF  256
#define OD  128

// ---------------- device scratch (no allocations allowed) ----------------
__device__ int   g_is64;
__device__ int   g_total;
__device__ int   g_rank[NE];         // arrival rank within destination bucket
__device__ int   g_srt[NE];
__device__ int   g_deg[NND];
__device__ int   g_start[NND];
__device__ float g_dinv[NND];
__device__ __half g_hb[(size_t)NND * OD];   // h scaled, fp16, 25.6 MB
__device__ __half g_wt[OD * KF];            // W^T fp16 [n][k]

__device__ __forceinline__ uint32_t smem_u32(const void* p) {
    uint32_t a;
    asm("{ .reg .u64 t; cvta.to.shared.u64 t, %1; cvt.u32.u64 %0, t; }"
        : "=r"(a) : "l"(p));
    return a;
}

#define CP_ASYNC16(dst, src) \
    asm volatile("cp.async.cg.shared.global [%0], [%1], 16;" \
                 :: "r"(dst), "l"(src) : "memory")
#define CP_COMMIT() asm volatile("cp.async.commit_group;" ::: "memory")
#define CP_WAIT0()  asm volatile("cp.async.wait_group 0;" ::: "memory")

// ---------------- launch 1: zero deg + dtype detect + W->fp16 ------------
__global__ void zero_wsplit_kernel(const void* ei, const float* __restrict__ W) {
    int i = blockIdx.x * blockDim.x + threadIdx.x;
    if (i < NND) g_deg[i] = 0;
    if (i == 0) {
        g_total = 0;
        const long long* p = (const long long*)ei;
        int ok64 = 1;
        #pragma unroll
        for (int j = 0; j < 16; j++) {
            long long v = p[j];
            if (v < 0 || v >= NND) ok64 = 0;
        }
        g_is64 = ok64;
    }
    if (i < KF * OD) {
        int k = i >> 7;
        int n = i & 127;
        g_wt[n * KF + k] = __float2half_rn(W[i]);   // W[k][n] coalesced read
    }
}

// ---------------- launch 2: degree count + rank (reads ei) ---------------
__global__ void conv_deg_kernel(const void* ei) {
    int e = blockIdx.x * blockDim.x + threadIdx.x;
    if (e >= NE) return;
    int c;
    if (g_is64) c = (int)((const long long*)ei)[e + NE];
    else        c = ((const int*)ei)[e + NE];
    g_rank[e] = atomicAdd(&g_deg[c], 1);
}

// ---------------- launch 3: offsets (warp-aggregated atomic) + dinv ------
__global__ void offset_dinv_kernel() {
    int i = blockIdx.x * blockDim.x + threadIdx.x;
    int lane = threadIdx.x & 31;
    int deg = (i < NND) ? g_deg[i] : 0;
    int s = deg;
    #pragma unroll
    for (int o = 1; o < 32; o <<= 1) {
        int t = __shfl_up_sync(0xffffffffu, s, o);
        if (lane >= o) s += t;
    }
    int total = __shfl_sync(0xffffffffu, s, 31);
    int base = 0;
    if (lane == 0) base = atomicAdd(&g_total, total);
    base = __shfl_sync(0xffffffffu, base, 0);
    if (i < NND) {
        g_start[i] = base + s - deg;
        g_dinv[i] = rsqrtf((float)(deg + 1));
    }
}

// ================= launch 4: GEMM (mma.sync fp16, 2-term split) =========
// CTA tile 64(M)x128(N), K chunks of 64. 8 warps in 2(M)x4(N) grid,
// warp tile 32x32. D = xh*W + xl*W (x = xh+xl fp16 exact), fp32 accum.
static constexpr int SA = 72;
static constexpr int TILE_A = 64 * SA;       // 4608 elems
static constexpr int TILE_B = 128 * SA;      // 9216 elems
static constexpr int SMEM_DYN = (4 * TILE_A + 2 * TILE_B) * 2;   // 73728 B

__device__ __forceinline__ unsigned pack_h2f(float a, float b) {
    __half2 h = __floats2half2_rn(a, b);
    return *(unsigned*)&h;
}
__device__ __forceinline__ unsigned pack_h2(__half a, __half b) {
    __half2 h = __halves2half2(a, b);
    return *(unsigned*)&h;
}

__device__ __forceinline__ void ldmx4(uint32_t addr, uint32_t* r) {
    asm volatile("ldmatrix.sync.aligned.m8n8.x4.shared.b16 {%0,%1,%2,%3}, [%4];"
                 : "=r"(r[0]), "=r"(r[1]), "=r"(r[2]), "=r"(r[3]) : "r"(addr));
}

__device__ __forceinline__ void mma16816h(float* d, const uint32_t* a,
                                          const uint32_t* b) {
    asm volatile(
        "mma.sync.aligned.m16n8k16.row.col.f32.f16.f16.f32 "
        "{%0,%1,%2,%3}, {%4,%5,%6,%7}, {%8,%9}, {%0,%1,%2,%3};"
        : "+f"(d[0]), "+f"(d[1]), "+f"(d[2]), "+f"(d[3])
        : "r"(a[0]), "r"(a[1]), "r"(a[2]), "r"(a[3]), "r"(b[0]), "r"(b[1]));
}

__global__ __launch_bounds__(256, 2) void gemm_mma_kernel(
    const float* __restrict__ x, const float* __restrict__ bias)
{
    extern __shared__ __half sm[];
    __half* sAh[2] = { sm,              sm + 2 * TILE_A };
    __half* sAl[2] = { sm + TILE_A,     sm + 3 * TILE_A };
    __half* sB[2]  = { sm + 4 * TILE_A, sm + 4 * TILE_A + TILE_B };

    const int tid = threadIdx.x;
    const int wid = tid >> 5;
    const int lane = tid & 31;
    const int wm = wid & 1;           // 0..1 -> rows wm*32
    const int wn = wid >> 1;          // 0..3 -> cols wn*32
    const int rowBase = blockIdx.x * 64;

    float acc[2][4][4];
    #pragma unroll
    for (int i = 0; i < 2; i++)
        #pragma unroll
        for (int j = 0; j < 4; j++)
            #pragma unroll
            for (int q = 0; q < 4; q++) acc[i][j][q] = 0.f;

    const int a_row_off = (lane & 7) + ((lane >> 3) & 1) * 8;
    const int a_col_off = ((lane >> 4) & 1) * 8;
    const int b_n_off   = (lane & 7) + ((lane >> 4) & 1) * 8;
    const int b_k_off   = ((lane >> 3) & 1) * 8;

    float4 areg[4];

    auto load_a = [&](int k0) {
        #pragma unroll
        for (int i = 0; i < 4; i++) {
            int g = tid + i * 256;           // 0..1023
            int r = g >> 4;                  // 0..63
            int f4 = g & 15;
            int grow = rowBase + r;
            areg[i] = make_float4(0.f, 0.f, 0.f, 0.f);
            if (grow < NND)
                areg[i] = *(const float4*)(x + (size_t)grow * KF + k0 + f4 * 4);
        }
    };
    auto store_a = [&](int buf) {
        #pragma unroll
        for (int i = 0; i < 4; i++) {
            int g = tid + i * 256;
            int r = g >> 4;
            int f4 = g & 15;
            float4 v = areg[i];
            __half hx = __float2half_rn(v.x);
            __half hy = __float2half_rn(v.y);
            __half hz = __float2half_rn(v.z);
            __half hw = __float2half_rn(v.w);
            __half lx = __float2half_rn(v.x - __half2float(hx));
            __half ly = __float2half_rn(v.y - __half2float(hy));
            __half lz = __float2half_rn(v.z - __half2float(hz));
            __half lw = __float2half_rn(v.w - __half2float(hw));
            int off = r * SA + f4 * 4;
            *(uint2*)(sAh[buf] + off) = make_uint2(pack_h2(hx, hy), pack_h2(hz, hw));
            *(uint2*)(sAl[buf] + off) = make_uint2(pack_h2(lx, ly), pack_h2(lz, lw));
        }
    };
    auto issue_b = [&](int k0, int buf) {
        uint32_t bb = smem_u32(sB[buf]);
        #pragma unroll
        for (int i = 0; i < 4; i++) {
            int g = tid + i * 256;           // 0..1023
            int n = g >> 3;                  // 0..127
            int f8 = g & 7;
            uint32_t doff = (uint32_t)(n * SA + f8 * 8) * 2;
            CP_ASYNC16(bb + doff, g_wt + (size_t)n * KF + k0 + f8 * 8);
        }
        CP_COMMIT();
    };

    load_a(0);
    issue_b(0, 0);
    store_a(0);
    CP_WAIT0();
    __syncthreads();

    for (int c = 0; c < 4; c++) {
        const int buf = c & 1;
        if (c < 3) {
            issue_b((c + 1) * 64, buf ^ 1);
            load_a((c + 1) * 64);
        }

        const uint32_t ah_b = smem_u32(sAh[buf]);
        const uint32_t al_b = smem_u32(sAl[buf]);
        const uint32_t b_b  = smem_u32(sB[buf]);

        #pragma unroll
        for (int ks = 0; ks < 4; ks++) {
            const int k = ks * 16;
            uint32_t af[2][2][4];            // [hi/lo][mtile][4]
            #pragma unroll
            for (int mt = 0; mt < 2; mt++) {
                int row = wm * 32 + mt * 16 + a_row_off;
                uint32_t byoff = (uint32_t)(row * SA + k + a_col_off) * 2;
                ldmx4(ah_b + byoff, af[0][mt]);
                ldmx4(al_b + byoff, af[1][mt]);
            }
            uint32_t bfg[2][4];              // [n16 group][4]
            #pragma unroll
            for (int j = 0; j < 2; j++) {
                int n = wn * 32 + j * 16 + b_n_off;
                uint32_t byoff = (uint32_t)(n * SA + k + b_k_off) * 2;
                ldmx4(b_b + byoff, bfg[j]);
            }
            #pragma unroll
            for (int mt = 0; mt < 2; mt++)
                #pragma unroll
                for (int j = 0; j < 2; j++)
                    #pragma unroll
                    for (int h = 0; h < 2; h++) {
                        int nt = j * 2 + h;
                        mma16816h(acc[mt][nt], af[0][mt], &bfg[j][h * 2]);
                        mma16816h(acc[mt][nt], af[1][mt], &bfg[j][h * 2]);
                    }
        }

        if (c < 3) {
            store_a(buf ^ 1);
            CP_WAIT0();
        }
        __syncthreads();
    }

    // ---- epilogue: hb = fp16( dinv[row] * (acc + bias) ) ----
    const int g4 = lane >> 2;
    const int ti = lane & 3;
    #pragma unroll
    for (int mt = 0; mt < 2; mt++) {
        int r0 = rowBase + wm * 32 + mt * 16 + g4;
        int r1 = r0 + 8;
        float d0 = (r0 < NND) ? g_dinv[r0] : 0.f;
        float d1 = (r1 < NND) ? g_dinv[r1] : 0.f;
        #pragma unroll
        for (int nt = 0; nt < 4; nt++) {
            int col = wn * 32 + nt * 8 + ti * 2;
            float b0 = bias[col], b1 = bias[col + 1];
            if (r0 < NND) {
                unsigned v = pack_h2f((acc[mt][nt][0] + b0) * d0,
                                      (acc[mt][nt][1] + b1) * d0);
                *(unsigned*)(g_hb + (size_t)r0 * OD + col) = v;
            }
            if (r1 < NND) {
                unsigned v = pack_h2f((acc[mt][nt][2] + b0) * d1,
                                      (acc[mt][nt][3] + b1) * d1);
                *(unsigned*)(g_hb + (size_t)r1 * OD + col) = v;
            }
        }
    }
}

// ---------------- launch 5: CSR fill (atomic-free, re-reads ei) ----------
__global__ void fill_kernel(const void* ei) {
    int e = blockIdx.x * blockDim.x + threadIdx.x;
    if (e >= NE) return;
    int r, c;
    if (g_is64) {
        const long long* p = (const long long*)ei;
        r = (int)p[e];
        c = (int)p[e + NE];
    } else {
        const int* p = (const int*)ei;
        r = p[e];
        c = p[e + NE];
    }
    g_srt[g_start[c] + g_rank[e]] = r;
}

// ---------------- launch 6: CSR aggregation (warp/node, fp16 gather) -----
__device__ __forceinline__ float4 h4_to_f4(uint2 v) {
    __half2 a = *(__half2*)&v.x;
    __half2 b = *(__half2*)&v.y;
    float2 fa = __half22float2(a);
    float2 fb = __half22float2(b);
    return make_float4(fa.x, fa.y, fb.x, fb.y);
}

__global__ __launch_bounds__(256) void agg_kernel(float* __restrict__ out) {
    int gid = blockIdx.x * 256 + threadIdx.x;
    int node = gid >> 5;
    if (node >= NND) return;
    int lane = threadIdx.x & 31;
    const __half* hb = g_hb + (size_t)lane * 4;

    float4 acc = h4_to_f4(*(const uint2*)(hb + (size_t)node * OD));

    int s = g_start[node];
    int e = s + g_deg[node];
    int i = s;
    for (; i + 4 <= e; i += 4) {
        int r0 = g_srt[i];
        int r1 = g_srt[i + 1];
        int r2 = g_srt[i + 2];
        int r3 = g_srt[i + 3];
        uint2 u0 = *(const uint2*)(hb + (size_t)r0 * OD);
        uint2 u1 = *(const uint2*)(hb + (size_t)r1 * OD);
        uint2 u2 = *(const uint2*)(hb + (size_t)r2 * OD);
        uint2 u3 = *(const uint2*)(hb + (size_t)r3 * OD);
        float4 v0 = h4_to_f4(u0);
        float4 v1 = h4_to_f4(u1);
        float4 v2 = h4_to_f4(u2);
        float4 v3 = h4_to_f4(u3);
        acc.x += (v0.x + v1.x) + (v2.x + v3.x);
        acc.y += (v0.y + v1.y) + (v2.y + v3.y);
        acc.z += (v0.z + v1.z) + (v2.z + v3.z);
        acc.w += (v0.w + v1.w) + (v2.w + v3.w);
    }
    for (; i < e; i++) {
        int r0 = g_srt[i];
        float4 v0 = h4_to_f4(*(const uint2*)(hb + (size_t)r0 * OD));
        acc.x += v0.x; acc.y += v0.y; acc.z += v0.z; acc.w += v0.w;
    }

    float d = g_dinv[node];
    float4 o;
    o.x = fmaxf(acc.x * d, 0.f);
    o.y = fmaxf(acc.y * d, 0.f);
    o.z = fmaxf(acc.z * d, 0.f);
    o.w = fmaxf(acc.w * d, 0.f);
    *(float4*)(out + (size_t)node * OD + lane * 4) = o;
}

// ---------------- launch ----------------
extern "C" void kernel_launch(void* const* d_in, const int* in_sizes, int n_in,
                              void* d_out, int out_size) {
    const float* x  = (const float*)d_in[0];
    const void*  ei = d_in[1];
    const float* W  = (const float*)d_in[2];
    const float* b  = (const float*)d_in[3];
    float* out = (float*)d_out;

    cudaFuncSetAttribute(gemm_mma_kernel,
                         cudaFuncAttributeMaxDynamicSharedMemorySize, SMEM_DYN);

    zero_wsplit_kernel<<<(NND + 255) / 256, 256>>>(ei, W);
    conv_deg_kernel<<<(NE + 255) / 256, 256>>>(ei);
    offset_dinv_kernel<<<(NND + 255) / 256, 256>>>();
    gemm_mma_kernel<<<(NND + 63) / 64, 256, SMEM_DYN>>>(x, b);
    fill_kernel<<<(NE + 255) / 256, 256>>>(ei);
    agg_kernel<<<(NND * 32 + 255) / 256, 256>>>(out);
}

// round 11
// speedup vs baseline: 3.5140x; 1.0944x over previous
#include <cuda_runtime.h>
#include <cuda_bf16.h>
#include <cuda_fp16.h>
#include <cstdint>

#define NND 100000
#define NE  1600000
#define KF  256
#define OD  128

// ---------------- device scratch (no allocations allowed) ----------------
__device__ int   g_is64;
__device__ int   g_total;
__device__ int   g_rank[NE];         // arrival rank within destination bucket
__device__ int   g_srt[NE];
__device__ int   g_deg[NND];
__device__ int   g_start[NND];
__device__ float g_dinv[NND];
__device__ __half g_hb[(size_t)NND * OD];   // h scaled, fp16, 25.6 MB
__device__ __half g_wt[OD * KF];            // W^T fp16 [n][k]

__device__ __forceinline__ uint32_t smem_u32(const void* p) {
    uint32_t a;
    asm("{ .reg .u64 t; cvta.to.shared.u64 t, %1; cvt.u32.u64 %0, t; }"
        : "=r"(a) : "l"(p));
    return a;
}

#define CP_ASYNC16(dst, src) \
    asm volatile("cp.async.cg.shared.global [%0], [%1], 16;" \
                 :: "r"(dst), "l"(src) : "memory")
#define CP_COMMIT() asm volatile("cp.async.commit_group;" ::: "memory")
#define CP_WAIT0()  asm volatile("cp.async.wait_group 0;" ::: "memory")

// ---------------- launch 1: zero deg + dtype detect + W->fp16 ------------
__global__ void zero_wsplit_kernel(const void* ei, const float* __restrict__ W) {
    int i = blockIdx.x * blockDim.x + threadIdx.x;
    if (i < NND) g_deg[i] = 0;
    if (i == 0) {
        g_total = 0;
        const long long* p = (const long long*)ei;
        int ok64 = 1;
        #pragma unroll
        for (int j = 0; j < 16; j++) {
            long long v = p[j];
            if (v < 0 || v >= NND) ok64 = 0;
        }
        g_is64 = ok64;
    }
    if (i < KF * OD) {
        int k = i >> 7;
        int n = i & 127;
        g_wt[n * KF + k] = __float2half_rn(W[i]);   // W[k][n] coalesced read
    }
}

// ---------------- launch 2: degree count + rank (reads ei) ---------------
__global__ void conv_deg_kernel(const void* ei) {
    int e = blockIdx.x * blockDim.x + threadIdx.x;
    if (e >= NE) return;
    int c;
    if (g_is64) c = (int)((const long long*)ei)[e + NE];
    else        c = ((const int*)ei)[e + NE];
    g_rank[e] = atomicAdd(&g_deg[c], 1);
}

// ---------------- launch 3: offsets (warp-aggregated atomic) + dinv ------
__global__ void offset_dinv_kernel() {
    int i = blockIdx.x * blockDim.x + threadIdx.x;
    int lane = threadIdx.x & 31;
    int deg = (i < NND) ? g_deg[i] : 0;
    int s = deg;
    #pragma unroll
    for (int o = 1; o < 32; o <<= 1) {
        int t = __shfl_up_sync(0xffffffffu, s, o);
        if (lane >= o) s += t;
    }
    int total = __shfl_sync(0xffffffffu, s, 31);
    int base = 0;
    if (lane == 0) base = atomicAdd(&g_total, total);
    base = __shfl_sync(0xffffffffu, base, 0);
    if (i < NND) {
        g_start[i] = base + s - deg;
        g_dinv[i] = rsqrtf((float)(deg + 1));
    }
}

// ================= launch 4: GEMM (mma.sync fp16, single-precision x) ====
// CTA tile 64(M)x128(N), K chunks of 64. 8 warps in 2(M)x4(N) grid,
// warp tile 32x32. D = x_f16 * W_f16, fp32 accum.
static constexpr int SA = 72;
static constexpr int TILE_A = 64 * SA;       // 4608 elems
static constexpr int TILE_B = 128 * SA;      // 9216 elems
static constexpr int SMEM_DYN = (2 * TILE_A + 2 * TILE_B) * 2;   // 55296 B

__device__ __forceinline__ unsigned pack_h2f(float a, float b) {
    __half2 h = __floats2half2_rn(a, b);
    return *(unsigned*)&h;
}

__device__ __forceinline__ void ldmx4(uint32_t addr, uint32_t* r) {
    asm volatile("ldmatrix.sync.aligned.m8n8.x4.shared.b16 {%0,%1,%2,%3}, [%4];"
                 : "=r"(r[0]), "=r"(r[1]), "=r"(r[2]), "=r"(r[3]) : "r"(addr));
}

__device__ __forceinline__ void mma16816h(float* d, const uint32_t* a,
                                          const uint32_t* b) {
    asm volatile(
        "mma.sync.aligned.m16n8k16.row.col.f32.f16.f16.f32 "
        "{%0,%1,%2,%3}, {%4,%5,%6,%7}, {%8,%9}, {%0,%1,%2,%3};"
        : "+f"(d[0]), "+f"(d[1]), "+f"(d[2]), "+f"(d[3])
        : "r"(a[0]), "r"(a[1]), "r"(a[2]), "r"(a[3]), "r"(b[0]), "r"(b[1]));
}

__global__ __launch_bounds__(256) void gemm_mma_kernel(
    const float* __restrict__ x, const float* __restrict__ bias)
{
    extern __shared__ __half sm[];
    __half* sA[2] = { sm,              sm + TILE_A };
    __half* sB[2] = { sm + 2 * TILE_A, sm + 2 * TILE_A + TILE_B };

    const int tid = threadIdx.x;
    const int wid = tid >> 5;
    const int lane = tid & 31;
    const int wm = wid & 1;           // 0..1 -> rows wm*32
    const int wn = wid >> 1;          // 0..3 -> cols wn*32
    const int rowBase = blockIdx.x * 64;

    float acc[2][4][4];
    #pragma unroll
    for (int i = 0; i < 2; i++)
        #pragma unroll
        for (int j = 0; j < 4; j++)
            #pragma unroll
            for (int q = 0; q < 4; q++) acc[i][j][q] = 0.f;

    const int a_row_off = (lane & 7) + ((lane >> 3) & 1) * 8;
    const int a_col_off = ((lane >> 4) & 1) * 8;
    const int b_n_off   = (lane & 7) + ((lane >> 4) & 1) * 8;
    const int b_k_off   = ((lane >> 3) & 1) * 8;

    float4 areg[4];

    auto load_a = [&](int k0) {
        #pragma unroll
        for (int i = 0; i < 4; i++) {
            int g = tid + i * 256;           // 0..1023
            int r = g >> 4;                  // 0..63
            int f4 = g & 15;
            int grow = rowBase + r;
            areg[i] = make_float4(0.f, 0.f, 0.f, 0.f);
            if (grow < NND)
                areg[i] = *(const float4*)(x + (size_t)grow * KF + k0 + f4 * 4);
        }
    };
    auto store_a = [&](int buf) {
        #pragma unroll
        for (int i = 0; i < 4; i++) {
            int g = tid + i * 256;
            int r = g >> 4;
            int f4 = g & 15;
            float4 v = areg[i];
            int off = r * SA + f4 * 4;
            *(uint2*)(sA[buf] + off) =
                make_uint2(pack_h2f(v.x, v.y), pack_h2f(v.z, v.w));
        }
    };
    auto issue_b = [&](int k0, int buf) {
        uint32_t bb = smem_u32(sB[buf]);
        #pragma unroll
        for (int i = 0; i < 4; i++) {
            int g = tid + i * 256;           // 0..1023
            int n = g >> 3;                  // 0..127
            int f8 = g & 7;
            uint32_t doff = (uint32_t)(n * SA + f8 * 8) * 2;
            CP_ASYNC16(bb + doff, g_wt + (size_t)n * KF + k0 + f8 * 8);
        }
        CP_COMMIT();
    };

    load_a(0);
    issue_b(0, 0);
    store_a(0);
    CP_WAIT0();
    __syncthreads();

    for (int c = 0; c < 4; c++) {
        const int buf = c & 1;
        if (c < 3) {
            issue_b((c + 1) * 64, buf ^ 1);
            load_a((c + 1) * 64);
        }

        const uint32_t a_b = smem_u32(sA[buf]);
        const uint32_t b_b = smem_u32(sB[buf]);

        #pragma unroll
        for (int ks = 0; ks < 4; ks++) {
            const int k = ks * 16;
            uint32_t af[2][4];               // [mtile][4]
            #pragma unroll
            for (int mt = 0; mt < 2; mt++) {
                int row = wm * 32 + mt * 16 + a_row_off;
                uint32_t byoff = (uint32_t)(row * SA + k + a_col_off) * 2;
                ldmx4(a_b + byoff, af[mt]);
            }
            uint32_t bfg[2][4];              // [n16 group][4]
            #pragma unroll
            for (int j = 0; j < 2; j++) {
                int n = wn * 32 + j * 16 + b_n_off;
                uint32_t byoff = (uint32_t)(n * SA + k + b_k_off) * 2;
                ldmx4(b_b + byoff, bfg[j]);
            }
            #pragma unroll
            for (int mt = 0; mt < 2; mt++)
                #pragma unroll
                for (int j = 0; j < 2; j++)
                    #pragma unroll
                    for (int h = 0; h < 2; h++)
                        mma16816h(acc[mt][j * 2 + h], af[mt], &bfg[j][h * 2]);
        }

        if (c < 3) {
            store_a(buf ^ 1);
            CP_WAIT0();
        }
        __syncthreads();
    }

    // ---- epilogue: hb = fp16( dinv[row] * (acc + bias) ) ----
    const int g4 = lane >> 2;
    const int ti = lane & 3;
    #pragma unroll
    for (int mt = 0; mt < 2; mt++) {
        int r0 = rowBase + wm * 32 + mt * 16 + g4;
        int r1 = r0 + 8;
        float d0 = (r0 < NND) ? g_dinv[r0] : 0.f;
        float d1 = (r1 < NND) ? g_dinv[r1] : 0.f;
        #pragma unroll
        for (int nt = 0; nt < 4; nt++) {
            int col = wn * 32 + nt * 8 + ti * 2;
            float b0 = bias[col], b1 = bias[col + 1];
            if (r0 < NND) {
                unsigned v = pack_h2f((acc[mt][nt][0] + b0) * d0,
                                      (acc[mt][nt][1] + b1) * d0);
                *(unsigned*)(g_hb + (size_t)r0 * OD + col) = v;
            }
            if (r1 < NND) {
                unsigned v = pack_h2f((acc[mt][nt][2] + b0) * d1,
                                      (acc[mt][nt][3] + b1) * d1);
                *(unsigned*)(g_hb + (size_t)r1 * OD + col) = v;
            }
        }
    }
}

// ---------------- launch 5: CSR fill (atomic-free, re-reads ei) ----------
__global__ void fill_kernel(const void* ei) {
    int e = blockIdx.x * blockDim.x + threadIdx.x;
    if (e >= NE) return;
    int r, c;
    if (g_is64) {
        const long long* p = (const long long*)ei;
        r = (int)p[e];
        c = (int)p[e + NE];
    } else {
        const int* p = (const int*)ei;
        r = p[e];
        c = p[e + NE];
    }
    g_srt[g_start[c] + g_rank[e]] = r;
}

// ---------------- launch 6: CSR aggregation (warp/node, fp16 gather) -----
__device__ __forceinline__ float4 h4_to_f4(uint2 v) {
    __half2 a = *(__half2*)&v.x;
    __half2 b = *(__half2*)&v.y;
    float2 fa = __half22float2(a);
    float2 fb = __half22float2(b);
    return make_float4(fa.x, fa.y, fb.x, fb.y);
}

__global__ __launch_bounds__(256) void agg_kernel(float* __restrict__ out) {
    int gid = blockIdx.x * 256 + threadIdx.x;
    int node = gid >> 5;
    if (node >= NND) return;
    int lane = threadIdx.x & 31;
    const __half* hb = g_hb + (size_t)lane * 4;

    float4 acc = h4_to_f4(*(const uint2*)(hb + (size_t)node * OD));

    int s = g_start[node];
    int e = s + g_deg[node];
    int i = s;
    for (; i + 4 <= e; i += 4) {
        int r0 = g_srt[i];
        int r1 = g_srt[i + 1];
        int r2 = g_srt[i + 2];
        int r3 = g_srt[i + 3];
        uint2 u0 = *(const uint2*)(hb + (size_t)r0 * OD);
        uint2 u1 = *(const uint2*)(hb + (size_t)r1 * OD);
        uint2 u2 = *(const uint2*)(hb + (size_t)r2 * OD);
        uint2 u3 = *(const uint2*)(hb + (size_t)r3 * OD);
        float4 v0 = h4_to_f4(u0);
        float4 v1 = h4_to_f4(u1);
        float4 v2 = h4_to_f4(u2);
        float4 v3 = h4_to_f4(u3);
        acc.x += (v0.x + v1.x) + (v2.x + v3.x);
        acc.y += (v0.y + v1.y) + (v2.y + v3.y);
        acc.z += (v0.z + v1.z) + (v2.z + v3.z);
        acc.w += (v0.w + v1.w) + (v2.w + v3.w);
    }
    for (; i < e; i++) {
        int r0 = g_srt[i];
        float4 v0 = h4_to_f4(*(const uint2*)(hb + (size_t)r0 * OD));
        acc.x += v0.x; acc.y += v0.y; acc.z += v0.z; acc.w += v0.w;
    }

    float d = g_dinv[node];
    float4 o;
    o.x = fmaxf(acc.x * d, 0.f);
    o.y = fmaxf(acc.y * d, 0.f);
    o.z = fmaxf(acc.z * d, 0.f);
    o.w = fmaxf(acc.w * d, 0.f);
    *(float4*)(out + (size_t)node * OD + lane * 4) = o;
}

// ---------------- launch ----------------
extern "C" void kernel_launch(void* const* d_in, const int* in_sizes, int n_in,
                              void* d_out, int out_size) {
    const float* x  = (const float*)d_in[0];
    const void*  ei = d_in[1];
    const float* W  = (const float*)d_in[2];
    const float* b  = (const float*)d_in[3];
    float* out = (float*)d_out;

    cudaFuncSetAttribute(gemm_mma_kernel,
                         cudaFuncAttributeMaxDynamicSharedMemorySize, SMEM_DYN);

    zero_wsplit_kernel<<<(NND + 255) / 256, 256>>>(ei, W);
    conv_deg_kernel<<<(NE + 255) / 256, 256>>>(ei);
    offset_dinv_kernel<<<(NND + 255) / 256, 256>>>();
    gemm_mma_kernel<<<(NND + 63) / 64, 256, SMEM_DYN>>>(x, b);
    fill_kernel<<<(NE + 255) / 256, 256>>>(ei);
    agg_kernel<<<(NND * 32 + 255) / 256, 256>>>(out);
}